// round 8
// baseline (speedup 1.0000x reference)
#include <cuda_runtime.h>
#include <cuda_fp16.h>
#include <cstdint>
#include <math.h>

// ---------------------------------------------------------------------------
// RWKV forward. GEMMs: mma.sync fp16, 2-product split (A = Ah+Al exact, B =
// fp16(W) single). R8: CTA 128x128, 256 threads, 2 CTAs/SM (desynchronized
// co-resident CTAs keep the tensor pipe fed through sync/ldmatrix bubbles).
// ---------------------------------------------------------------------------

#define E_DIM   1024
#define FOUR_E  4096
#define D_IN    512
#define BTOK    4096
#define T_LEN   1024
#define BATCH   4
#define NLAYER  11
#define NCHUNK  16
#define CHLEN   64

// ---------------- device-global scratch (no allocation allowed) ------------
#define WBUF_ELEMS 157810688ull
__device__ __half g_wf[WBUF_ELEMS];

__device__ __half g_inh[BTOK * D_IN],   g_inl[BTOK * D_IN];
__device__ __half g_xnh[BTOK * E_DIM],  g_xnl[BTOK * E_DIM];
__device__ __half g_hbh[BTOK * FOUR_E], g_hbl[BTOK * FOUR_E];
__device__ __half g_yh [BTOK * E_DIM],  g_yl [BTOK * E_DIM];

__device__ float g_res[BTOK * E_DIM];
__device__ float g_tmp[BTOK * E_DIM];
__device__ float g_k  [BTOK * E_DIM];
__device__ float g_r  [BTOK * E_DIM];
__device__ float g_st [BATCH * NCHUNK * 3 * E_DIM];

// ---------------------------------------------------------------------------
// helpers
// ---------------------------------------------------------------------------
__device__ __forceinline__ uint32_t smem_u32(const void* p) {
    uint32_t a;
    asm("{ .reg .u64 t; cvta.to.shared.u64 t, %1; cvt.u32.u64 %0, t; }" : "=r"(a) : "l"(p));
    return a;
}
__device__ __forceinline__ void ldm_x4(uint32_t* r, uint32_t addr) {
    asm volatile("ldmatrix.sync.aligned.m8n8.x4.shared.b16 {%0,%1,%2,%3}, [%4];"
        : "=r"(r[0]), "=r"(r[1]), "=r"(r[2]), "=r"(r[3]) : "r"(addr));
}
__device__ __forceinline__ void mma_f16(float* d, const uint32_t* a, uint32_t b0, uint32_t b1) {
    asm volatile("mma.sync.aligned.m16n8k16.row.col.f32.f16.f16.f32 "
        "{%0,%1,%2,%3}, {%4,%5,%6,%7}, {%8,%9}, {%0,%1,%2,%3};"
        : "+f"(d[0]), "+f"(d[1]), "+f"(d[2]), "+f"(d[3])
        : "r"(a[0]), "r"(a[1]), "r"(a[2]), "r"(a[3]), "r"(b0), "r"(b1));
}
__device__ __forceinline__ void cp16(uint32_t s, const void* g) {
    asm volatile("cp.async.cg.shared.global [%0], [%1], 16;" :: "r"(s), "l"(g));
}
__device__ __forceinline__ void cp_commit() {
    asm volatile("cp.async.commit_group;" ::: "memory");
}
template <int N> __device__ __forceinline__ void cp_wait() {
    asm volatile("cp.async.wait_group %0;" :: "n"(N) : "memory");
}
// float2 -> fp16x2 hi (rn) + fp16x2 lo (exact residual, rn)
__device__ __forceinline__ void splith2(float2 v, uint32_t& h, uint32_t& l) {
    __half2 hh = __floats2half2_rn(v.x, v.y);
    h = *reinterpret_cast<uint32_t*>(&hh);
    float2 b = __half22float2(hh);
    __half2 ll = __floats2half2_rn(v.x - b.x, v.y - b.y);
    l = *reinterpret_cast<uint32_t*>(&ll);
}
__device__ __forceinline__ uint32_t h2pack(float a, float b) {
    __half2 h = __floats2half2_rn(a, b);
    return *reinterpret_cast<uint32_t*>(&h);
}

// ---------------------------------------------------------------------------
// weight conversion: fp32 -> fp16, all tensors in ONE launch (job table)
// ---------------------------------------------------------------------------
#define NJOBS 13
struct ConvJobs {
    const float* src[NJOBS];
    unsigned long long n[NJOBS];
    unsigned long long ofs[NJOBS];
};

__global__ void convert_w(ConvJobs jobs, __half* __restrict__ dst)
{
    const int jid = blockIdx.y;
    const float4* src = reinterpret_cast<const float4*>(jobs.src[jid]);
    uint4* d = reinterpret_cast<uint4*>(dst + jobs.ofs[jid]);
    const long long n8 = (long long)(jobs.n[jid] >> 3);
    const long long stride = (long long)gridDim.x * blockDim.x;
    for (long long i = blockIdx.x * (long long)blockDim.x + threadIdx.x; i < n8; i += stride) {
        float4 a = src[2 * i];
        float4 b = src[2 * i + 1];
        uint4 o;
        o.x = h2pack(a.x, a.y); o.y = h2pack(a.z, a.w);
        o.z = h2pack(b.x, b.y); o.w = h2pack(b.z, b.w);
        d[i] = o;
    }
}

__global__ void convert_pair(const float4* __restrict__ src,
                             uint2* __restrict__ h, uint2* __restrict__ l, int n4)
{
    const int stride = gridDim.x * blockDim.x;
    for (int i = blockIdx.x * blockDim.x + threadIdx.x; i < n4; i += stride) {
        float4 v = src[i];
        uint2 hh, ll;
        splith2(make_float2(v.x, v.y), hh.x, ll.x);
        splith2(make_float2(v.z, v.w), hh.y, ll.y);
        h[i] = hh;
        l[i] = ll;
    }
}

// ---------------------------------------------------------------------------
// GEMM: C[M,N] = A[M,K] @ W[N,K]^T. A = fp16 h/l pair, B = fp16 single.
// CTA 128x128x32, 256 threads (8 warps: 4m x 2n), warp tile 32x64, 3 stages,
// 2 CTAs per SM.
// ---------------------------------------------------------------------------
#define TM 128
#define TN 128
#define TK 32
#define GT 256
#define STAGES 3

#define ROWB   80
#define OFF_AH 0
#define OFF_AL (128 * ROWB)
#define OFF_B  (2 * 128 * ROWB)
#define STAGE_SZ (3 * 128 * ROWB)          // 30720
#define GEMM_SMEM (STAGES * STAGE_SZ)      // 92160 (x2 CTAs = 184320/SM)

#define EPI_NONE   0
#define EPI_BIAS   1
#define EPI_RELUSQ 2
#define EPI_ADD    3
#define EPI_CMIX   4

template <int EPI>
__global__ __launch_bounds__(GT, 2)
void gemm_f16(const __half* __restrict__ Ah, const __half* __restrict__ Al,
              const __half* __restrict__ Bh,
              float* __restrict__ C, int M, int N, int K,
              const float* __restrict__ bias,
              const float* __restrict__ Cin,
              const float* __restrict__ Rg,
              __half* __restrict__ Oh, __half* __restrict__ Ol)
{
    extern __shared__ char smem[];
    const uint32_t sbase = smem_u32(smem);
    const int tid  = threadIdx.x;
    const int lane = tid & 31;
    const int wid  = tid >> 5;
    const int wm   = wid & 3;    // 4 warps in m (32 rows each)
    const int wn   = wid >> 2;   // 2 warps in n (64 cols each)
    const int bm   = blockIdx.y * TM;
    const int bn   = blockIdx.x * TN;

    const int lrow  = lane & 15;
    const int lchun = lane >> 4;

    float acc[2][8][4];
#pragma unroll
    for (int i = 0; i < 2; i++)
#pragma unroll
        for (int j = 0; j < 8; j++)
#pragma unroll
            for (int q = 0; q < 4; q++) acc[i][j][q] = 0.f;

    const int S = K / TK;

    auto issue = [&](int s, int buf) {
        const uint32_t sb = sbase + buf * STAGE_SZ;
        const int k0 = s * TK;
        // A h + l: 128 rows x 4 segs = 512 slots each, 2 iters/thread each
#pragma unroll
        for (int i = 0; i < 2; i++) {
            int idx = tid + i * GT;
            int row = idx >> 2, seg = idx & 3;
            uint32_t sa = sb + OFF_AH + row * ROWB + seg * 16;
            size_t go = (size_t)(bm + row) * K + k0 + seg * 8;
            cp16(sa, Ah + go);
            cp16(sa + (OFF_AL - OFF_AH), Al + go);
        }
        // B: 128 rows x 4 segs = 512 slots, 2 iters/thread
#pragma unroll
        for (int i = 0; i < 2; i++) {
            int idx = tid + i * GT;
            int row = idx >> 2, seg = idx & 3;
            uint32_t sa = sb + OFF_B + row * ROWB + seg * 16;
            size_t go = (size_t)(bn + row) * K + k0 + seg * 8;
            cp16(sa, Bh + go);
        }
        cp_commit();
    };

    issue(0, 0);
    issue(1, 1);

    for (int s = 0; s < S; s++) {
        const int buf = s % STAGES;
        cp_wait<1>();
        __syncthreads();

        const uint32_t sb = sbase + buf * STAGE_SZ;
#pragma unroll
        for (int kk = 0; kk < 2; kk++) {
            const uint32_t koff = (uint32_t)((kk * 2 + lchun) * 16);
            uint32_t ah[2][4], al[2][4];
#pragma unroll
            for (int mt = 0; mt < 2; mt++) {
                uint32_t aa = sb + OFF_AH + (uint32_t)((wm * 32 + mt * 16 + lrow) * ROWB) + koff;
                ldm_x4(ah[mt], aa);
                ldm_x4(al[mt], aa + (OFF_AL - OFF_AH));
            }
#pragma unroll
            for (int bg = 0; bg < 2; bg++) {
                uint32_t bh[2][4];
#pragma unroll
                for (int bt = 0; bt < 2; bt++) {
                    uint32_t ba = sb + OFF_B +
                        (uint32_t)((wn * 64 + (bg * 2 + bt) * 16 + lrow) * ROWB) + koff;
                    ldm_x4(bh[bt], ba);
                }
                // product passes: 8 independent accumulator chains per pass
#pragma unroll
                for (int mt = 0; mt < 2; mt++)
#pragma unroll
                    for (int bt = 0; bt < 2; bt++)
#pragma unroll
                        for (int j = 0; j < 2; j++)
                            mma_f16(acc[mt][bg * 4 + bt * 2 + j], ah[mt], bh[bt][j], bh[bt][2 + j]);
#pragma unroll
                for (int mt = 0; mt < 2; mt++)
#pragma unroll
                    for (int bt = 0; bt < 2; bt++)
#pragma unroll
                        for (int j = 0; j < 2; j++)
                            mma_f16(acc[mt][bg * 4 + bt * 2 + j], al[mt], bh[bt][j], bh[bt][2 + j]);
            }
        }
        if (s + 2 < S) issue(s + 2, (s + 2) % STAGES);
    }

    // epilogue
#pragma unroll
    for (int mt = 0; mt < 2; mt++)
#pragma unroll
        for (int nt = 0; nt < 8; nt++) {
            const int row0 = bm + wm * 32 + mt * 16 + (lane >> 2);
            const int col  = bn + wn * 64 + (nt >> 1) * 16 + (nt & 1) * 8 + (lane & 3) * 2;
#pragma unroll
            for (int h = 0; h < 2; h++) {
                const int r = row0 + h * 8;
                const size_t idx = (size_t)r * N + col;
                float2 v = make_float2(acc[mt][nt][2 * h + 0], acc[mt][nt][2 * h + 1]);
                if (EPI == EPI_BIAS) {
                    float2 bb = *reinterpret_cast<const float2*>(bias + col);
                    v.x += bb.x; v.y += bb.y;
                    *reinterpret_cast<float2*>(C + idx) = v;
                }
                if (EPI == EPI_NONE) {
                    *reinterpret_cast<float2*>(C + idx) = v;
                }
                if (EPI == EPI_RELUSQ) {
                    v.x = v.x > 0.f ? v.x * v.x : 0.f;
                    v.y = v.y > 0.f ? v.y * v.y : 0.f;
                    uint32_t hh, ll;
                    splith2(v, hh, ll);
                    *reinterpret_cast<uint32_t*>(Oh + idx) = hh;
                    *reinterpret_cast<uint32_t*>(Ol + idx) = ll;
                }
                if (EPI == EPI_ADD) {
                    float2 ci = *reinterpret_cast<const float2*>(Cin + idx);
                    v.x += ci.x; v.y += ci.y;
                    *reinterpret_cast<float2*>(C + idx) = v;
                }
                if (EPI == EPI_CMIX) {
                    float2 ci = *reinterpret_cast<const float2*>(Cin + idx);
                    float2 rr = *reinterpret_cast<const float2*>(Rg + idx);
                    v.x = ci.x + v.x * (1.f / (1.f + expf(-rr.x)));
                    v.y = ci.y + v.y * (1.f / (1.f + expf(-rr.y)));
                    *reinterpret_cast<float2*>(C + idx) = v;
                }
            }
        }
}

// ---------------------------------------------------------------------------
// LayerNorm over E=1024; optional fp32 out and/or fp16 h/l out.
// ---------------------------------------------------------------------------
__global__ __launch_bounds__(256)
void ln_kernel(const float* __restrict__ x, float* __restrict__ o,
               __half* __restrict__ oh, __half* __restrict__ ol,
               const float* __restrict__ g, const float* __restrict__ b)
{
    __shared__ float sm[18];
    const int row = blockIdx.x;
    const int t   = threadIdx.x;
    float4 v = reinterpret_cast<const float4*>(x + (size_t)row * E_DIM)[t];
    float s  = v.x + v.y + v.z + v.w;
    float ss = v.x * v.x + v.y * v.y + v.z * v.z + v.w * v.w;
#pragma unroll
    for (int off = 16; off > 0; off >>= 1) {
        s  += __shfl_xor_sync(0xffffffffu, s, off);
        ss += __shfl_xor_sync(0xffffffffu, ss, off);
    }
    const int wp = t >> 5, lane = t & 31;
    if (lane == 0) { sm[wp] = s; sm[8 + wp] = ss; }
    __syncthreads();
    if (t < 32) {
        s  = (t < 8) ? sm[t]     : 0.f;
        ss = (t < 8) ? sm[8 + t] : 0.f;
#pragma unroll
        for (int off = 4; off > 0; off >>= 1) {
            s  += __shfl_xor_sync(0xffffffffu, s, off);
            ss += __shfl_xor_sync(0xffffffffu, ss, off);
        }
        if (t == 0) {
            float mean = s * (1.f / E_DIM);
            float var  = ss * (1.f / E_DIM) - mean * mean;
            sm[16] = mean;
            sm[17] = rsqrtf(var + 1e-5f);
        }
    }
    __syncthreads();
    const float mean = sm[16], inv = sm[17];
    float4 gg = reinterpret_cast<const float4*>(g)[t];
    float4 bb = reinterpret_cast<const float4*>(b)[t];
    float4 ov;
    ov.x = (v.x - mean) * inv * gg.x + bb.x;
    ov.y = (v.y - mean) * inv * gg.y + bb.y;
    ov.z = (v.z - mean) * inv * gg.z + bb.z;
    ov.w = (v.w - mean) * inv * gg.w + bb.w;
    if (o) reinterpret_cast<float4*>(o + (size_t)row * E_DIM)[t] = ov;
    if (oh) {
        uint2 hh, ll;
        splith2(make_float2(ov.x, ov.y), hh.x, ll.x);
        splith2(make_float2(ov.z, ov.w), hh.y, ll.y);
        reinterpret_cast<uint2*>(oh + (size_t)row * E_DIM)[t] = hh;
        reinterpret_cast<uint2*>(ol + (size_t)row * E_DIM)[t] = ll;
    }
}

// ---------------------------------------------------------------------------
// WKV recurrence, exact chunked 2-pass scan. pass2 emits sigmoid(r)*wkv as
// fp16 h/l (input to the Wo GEMM).
// ---------------------------------------------------------------------------
__global__ __launch_bounds__(128)
void wkv_pass1(const float* __restrict__ k, const float* __restrict__ v,
               const float* __restrict__ decay, float* __restrict__ st)
{
    const int e = blockIdx.x * blockDim.x + threadIdx.x;
    const int c = blockIdx.y, b = blockIdx.z;
    const float w = -expf(decay[e]);
    float aa = 0.f, bb = 0.f, pp = -1e38f;
    const size_t base = ((size_t)b * T_LEN + (size_t)c * CHLEN) * E_DIM + e;
    const float* kp = k + base;
    const float* vp = v + base;
#pragma unroll 4
    for (int t = 0; t < CHLEN; t++) {
        float kt = kp[(size_t)t * E_DIM];
        float vt = vp[(size_t)t * E_DIM];
        float ww = pp + w;
        float p  = fmaxf(ww, kt);
        float e1 = expf(ww - p);
        float e2 = expf(kt - p);
        aa = e1 * aa + e2 * vt;
        bb = e1 * bb + e2;
        pp = p;
    }
    float* s = st + ((size_t)(b * NCHUNK + c) * 3) * E_DIM + e;
    s[0] = aa; s[E_DIM] = bb; s[2 * E_DIM] = pp;
}

__global__ __launch_bounds__(128)
void wkv_pass2(const float* __restrict__ k, const float* __restrict__ v,
               const float* __restrict__ decay, const float* __restrict__ first,
               const float* __restrict__ st,
               __half* __restrict__ yh, __half* __restrict__ yl)
{
    const int e = blockIdx.x * blockDim.x + threadIdx.x;
    const int c = blockIdx.y, b = blockIdx.z;
    const float w = -expf(decay[e]);
    const float u = first[e];
    float aa = 0.f, bb = 0.f, pp = -1e38f;
    for (int j = 0; j < c; j++) {
        const float* s = st + ((size_t)(b * NCHUNK + j) * 3) * E_DIM + e;
        float pd = pp + (float)CHLEN * w;
        float a2 = s[0], b2 = s[E_DIM], p2 = s[2 * E_DIM];
        float p  = fmaxf(pd, p2);
        float e1 = expf(pd - p), e2 = expf(p2 - p);
        aa = e1 * aa + e2 * a2;
        bb = e1 * bb + e2 * b2;
        pp = p;
    }
    const size_t base = ((size_t)b * T_LEN + (size_t)c * CHLEN) * E_DIM + e;
    const float* kp = k + base;
    const float* vp = v + base;
    for (int t = 0; t < CHLEN; t++) {
        float kt = kp[(size_t)t * E_DIM];
        float vt = vp[(size_t)t * E_DIM];   // v == r in this model
        float ww = u + kt;
        float p  = fmaxf(pp, ww);
        float e1 = expf(pp - p), e2 = expf(ww - p);
        float yt = (e1 * aa + e2 * vt) / (e1 * bb + e2);
        float ys = yt * (1.f / (1.f + expf(-vt)));
        const size_t off = base + (size_t)t * E_DIM;
        __half hi = __float2half_rn(ys);
        yh[off] = hi;
        yl[off] = __float2half_rn(ys - __half2float(hi));
        float ww2 = pp + w;
        float p2  = fmaxf(ww2, kt);
        e1 = expf(ww2 - p2); e2 = expf(kt - p2);
        aa = e1 * aa + e2 * vt;
        bb = e1 * bb + e2;
        pp = p2;
    }
}

// ---------------------------------------------------------------------------
// Host orchestration
// ---------------------------------------------------------------------------
static void set_smem_attrs() {
    cudaFuncSetAttribute(gemm_f16<EPI_NONE>,   cudaFuncAttributeMaxDynamicSharedMemorySize, GEMM_SMEM);
    cudaFuncSetAttribute(gemm_f16<EPI_BIAS>,   cudaFuncAttributeMaxDynamicSharedMemorySize, GEMM_SMEM);
    cudaFuncSetAttribute(gemm_f16<EPI_RELUSQ>, cudaFuncAttributeMaxDynamicSharedMemorySize, GEMM_SMEM);
    cudaFuncSetAttribute(gemm_f16<EPI_ADD>,    cudaFuncAttributeMaxDynamicSharedMemorySize, GEMM_SMEM);
    cudaFuncSetAttribute(gemm_f16<EPI_CMIX>,   cudaFuncAttributeMaxDynamicSharedMemorySize, GEMM_SMEM);
}

extern "C" void kernel_launch(void* const* d_in, const int* in_sizes, int n_in,
                              void* d_out, int out_size)
{
    const float* inp    = (const float*)d_in[0];
    const float* W_in   = (const float*)d_in[1];
    const float* b_in   = (const float*)d_in[2];
    const float* ln0g   = (const float*)d_in[3];
    const float* ln0b   = (const float*)d_in[4];
    const float* l0ln1g = (const float*)d_in[5];
    const float* l0ln1b = (const float*)d_in[6];
    const float* l0ln2g = (const float*)d_in[7];
    const float* l0ln2b = (const float*)d_in[8];
    const float* l0cmk  = (const float*)d_in[9];
    const float* l0cmv  = (const float*)d_in[10];
    const float* l0cmr  = (const float*)d_in[11];
    const float* l0ffk  = (const float*)d_in[12];
    const float* l0ffv  = (const float*)d_in[13];
    const float* l0ffr  = (const float*)d_in[14];
    const float* tmk    = (const float*)d_in[15];
    const float* tmr    = (const float*)d_in[16];
    const float* tmo    = (const float*)d_in[17];
    const float* tmdec  = (const float*)d_in[18];
    const float* tmfst  = (const float*)d_in[19];
    const float* ln1g   = (const float*)d_in[20];
    const float* ln1b   = (const float*)d_in[21];
    const float* ln2g   = (const float*)d_in[22];
    const float* ln2b   = (const float*)d_in[23];
    const float* ffk    = (const float*)d_in[24];
    const float* ffv    = (const float*)d_in[25];
    const float* ffr    = (const float*)d_in[26];
    const float* outg   = (const float*)d_in[27];
    const float* outb   = (const float*)d_in[28];
    float* out = (float*)d_out;

    set_smem_attrs();

    __half *wf, *inh, *inl, *xnh, *xnl, *hbh, *hbl, *yh, *yl;
    float *res, *tmp, *kb, *rb, *st;
    cudaGetSymbolAddress((void**)&wf,  g_wf);
    cudaGetSymbolAddress((void**)&inh, g_inh);
    cudaGetSymbolAddress((void**)&inl, g_inl);
    cudaGetSymbolAddress((void**)&xnh, g_xnh);
    cudaGetSymbolAddress((void**)&xnl, g_xnl);
    cudaGetSymbolAddress((void**)&hbh, g_hbh);
    cudaGetSymbolAddress((void**)&hbl, g_hbl);
    cudaGetSymbolAddress((void**)&yh,  g_yh);
    cudaGetSymbolAddress((void**)&yl,  g_yl);
    cudaGetSymbolAddress((void**)&res, g_res);
    cudaGetSymbolAddress((void**)&tmp, g_tmp);
    cudaGetSymbolAddress((void**)&kb,  g_k);
    cudaGetSymbolAddress((void**)&rb,  g_r);
    cudaGetSymbolAddress((void**)&st,  g_st);

    // ---- weight conversion: one job-table launch ----
    ConvJobs jobs;
    size_t off = 0;
    int ji = 0;
    auto addjob = [&](const float* src, size_t n) -> size_t {
        size_t o = off;
        jobs.src[ji] = src;
        jobs.n[ji]   = (unsigned long long)n;
        jobs.ofs[ji] = (unsigned long long)o;
        ji++;
        off += n;
        return o;
    };
    const size_t o_win  = addjob(W_in,  (size_t)E_DIM * D_IN);
    const size_t o_cmk  = addjob(l0cmk, (size_t)FOUR_E * E_DIM);
    const size_t o_cmv  = addjob(l0cmv, (size_t)E_DIM * FOUR_E);
    const size_t o_cmr  = addjob(l0cmr, (size_t)E_DIM * E_DIM);
    const size_t o_lffk = addjob(l0ffk, (size_t)FOUR_E * E_DIM);
    const size_t o_lffv = addjob(l0ffv, (size_t)E_DIM * FOUR_E);
    const size_t o_lffr = addjob(l0ffr, (size_t)E_DIM * E_DIM);
    const size_t o_tmk  = addjob(tmk, (size_t)NLAYER * E_DIM * E_DIM);
    const size_t o_tmr  = addjob(tmr, (size_t)NLAYER * E_DIM * E_DIM);
    const size_t o_tmo  = addjob(tmo, (size_t)NLAYER * E_DIM * E_DIM);
    const size_t o_ffk  = addjob(ffk, (size_t)NLAYER * FOUR_E * E_DIM);
    const size_t o_ffv  = addjob(ffv, (size_t)NLAYER * E_DIM * FOUR_E);
    const size_t o_ffr  = addjob(ffr, (size_t)NLAYER * E_DIM * E_DIM);
    convert_w<<<dim3(1184, NJOBS), 256>>>(jobs, wf);
    convert_pair<<<1024, 256>>>((const float4*)inp, (uint2*)inh, (uint2*)inl,
                                (int)((size_t)BTOK * D_IN / 4));

    const dim3 gE  (E_DIM  / TN, BTOK / TM);  // (8, 32) = 256 CTAs
    const dim3 g4E (FOUR_E / TN, BTOK / TM);  // (32, 32) = 1024 CTAs
    const dim3 gWKV(E_DIM / 128, NCHUNK, BATCH);

    // x = inputs @ W_in^T + b_in ; res = LN(x, ln0)
    gemm_f16<EPI_BIAS><<<gE, GT, GEMM_SMEM>>>(inh, inl, wf + o_win,
        tmp, BTOK, E_DIM, D_IN, b_in, nullptr, nullptr, nullptr, nullptr);
    ln_kernel<<<BTOK, 256>>>(tmp, res, nullptr, nullptr, ln0g, ln0b);

    auto cmix = [&](const float* lg, const float* lb,
                    size_t ok, size_t ov, size_t orr) {
        ln_kernel<<<BTOK, 256>>>(res, nullptr, xnh, xnl, lg, lb);
        gemm_f16<EPI_RELUSQ><<<g4E, GT, GEMM_SMEM>>>(xnh, xnl, wf + ok,
            nullptr, BTOK, FOUR_E, E_DIM, nullptr, nullptr, nullptr, hbh, hbl);
        gemm_f16<EPI_NONE><<<gE, GT, GEMM_SMEM>>>(xnh, xnl, wf + orr,
            rb, BTOK, E_DIM, E_DIM, nullptr, nullptr, nullptr, nullptr, nullptr);
        gemm_f16<EPI_CMIX><<<gE, GT, GEMM_SMEM>>>(hbh, hbl, wf + ov,
            res, BTOK, E_DIM, FOUR_E, nullptr, res, rb, nullptr, nullptr);
    };

    cmix(l0ln1g, l0ln1b, o_cmk, o_cmv, o_cmr);
    cmix(l0ln2g, l0ln2b, o_lffk, o_lffv, o_lffr);

    for (int l = 0; l < NLAYER; l++) {
        const size_t oEE = (size_t)l * E_DIM * E_DIM;
        const size_t o4E = (size_t)l * FOUR_E * E_DIM;
        const size_t oE  = (size_t)l * E_DIM;

        ln_kernel<<<BTOK, 256>>>(res, nullptr, xnh, xnl, ln1g + oE, ln1b + oE);
        gemm_f16<EPI_NONE><<<gE, GT, GEMM_SMEM>>>(xnh, xnl, wf + o_tmk + oEE,
            kb, BTOK, E_DIM, E_DIM, nullptr, nullptr, nullptr, nullptr, nullptr);
        gemm_f16<EPI_NONE><<<gE, GT, GEMM_SMEM>>>(xnh, xnl, wf + o_tmr + oEE,
            rb, BTOK, E_DIM, E_DIM, nullptr, nullptr, nullptr, nullptr, nullptr);
        wkv_pass1<<<gWKV, 128>>>(kb, rb, tmdec + oE, st);
        wkv_pass2<<<gWKV, 128>>>(kb, rb, tmdec + oE, tmfst + oE, st, yh, yl);
        gemm_f16<EPI_ADD><<<gE, GT, GEMM_SMEM>>>(yh, yl, wf + o_tmo + oEE,
            res, BTOK, E_DIM, E_DIM, nullptr, res, nullptr, nullptr, nullptr);

        ln_kernel<<<BTOK, 256>>>(res, nullptr, xnh, xnl, ln2g + oE, ln2b + oE);
        gemm_f16<EPI_RELUSQ><<<g4E, GT, GEMM_SMEM>>>(xnh, xnl, wf + o_ffk + o4E,
            nullptr, BTOK, FOUR_E, E_DIM, nullptr, nullptr, nullptr, hbh, hbl);
        gemm_f16<EPI_NONE><<<gE, GT, GEMM_SMEM>>>(xnh, xnl, wf + o_ffr + oEE,
            rb, BTOK, E_DIM, E_DIM, nullptr, nullptr, nullptr, nullptr, nullptr);
        gemm_f16<EPI_CMIX><<<gE, GT, GEMM_SMEM>>>(hbh, hbl, wf + o_ffv + o4E,
            res, BTOK, E_DIM, FOUR_E, nullptr, res, rb, nullptr, nullptr);
    }

    ln_kernel<<<BTOK, 256>>>(res, out, nullptr, nullptr, outg, outb);
}

// round 9
// speedup vs baseline: 1.2722x; 1.2722x over previous
#include <cuda_runtime.h>
#include <cuda_fp16.h>
#include <cstdint>
#include <math.h>

// ---------------------------------------------------------------------------
// RWKV forward. GEMMs: mma.sync fp16. 2-product split (A=Ah+Al exact) for
// GEMMs feeding exp/relu^2; single-product for o/ffv GEMMs (A-side is our own
// fp16 intermediate). k+r and ffk+ffr fused into single wide GEMMs.
// ---------------------------------------------------------------------------

#define E_DIM   1024
#define FOUR_E  4096
#define D_IN    512
#define BTOK    4096
#define T_LEN   1024
#define BATCH   4
#define NLAYER  11
#define NCHUNK  16
#define CHLEN   64

#define EE_  1048576ull          // E*E
#define FE_  4194304ull          // 4E*E
#define KRL_ (2ull * EE_)        // fused k+r block per layer
#define FFL_ (FE_ + EE_)         // fused ffk+ffr block per layer

// ---------------- device-global scratch (no allocation allowed) ------------
#define WBUF_ELEMS 157810688ull
__device__ __half g_wf[WBUF_ELEMS];

__device__ __half g_inh[BTOK * D_IN],   g_inl[BTOK * D_IN];
__device__ __half g_xnh[BTOK * E_DIM],  g_xnl[BTOK * E_DIM];
__device__ __half g_hbh[BTOK * FOUR_E];
__device__ __half g_yh [BTOK * E_DIM];

__device__ float g_res[BTOK * E_DIM];
__device__ float g_tmp[BTOK * E_DIM];
__device__ float g_kr [BTOK * 2 * E_DIM];
__device__ float g_r  [BTOK * E_DIM];
__device__ float g_st [BATCH * NCHUNK * 3 * E_DIM];

// ---------------------------------------------------------------------------
// helpers
// ---------------------------------------------------------------------------
__device__ __forceinline__ uint32_t smem_u32(const void* p) {
    uint32_t a;
    asm("{ .reg .u64 t; cvta.to.shared.u64 t, %1; cvt.u32.u64 %0, t; }" : "=r"(a) : "l"(p));
    return a;
}
__device__ __forceinline__ void ldm_x4(uint32_t* r, uint32_t addr) {
    asm volatile("ldmatrix.sync.aligned.m8n8.x4.shared.b16 {%0,%1,%2,%3}, [%4];"
        : "=r"(r[0]), "=r"(r[1]), "=r"(r[2]), "=r"(r[3]) : "r"(addr));
}
__device__ __forceinline__ void mma_f16(float* d, const uint32_t* a, uint32_t b0, uint32_t b1) {
    asm volatile("mma.sync.aligned.m16n8k16.row.col.f32.f16.f16.f32 "
        "{%0,%1,%2,%3}, {%4,%5,%6,%7}, {%8,%9}, {%0,%1,%2,%3};"
        : "+f"(d[0]), "+f"(d[1]), "+f"(d[2]), "+f"(d[3])
        : "r"(a[0]), "r"(a[1]), "r"(a[2]), "r"(a[3]), "r"(b0), "r"(b1));
}
__device__ __forceinline__ void cp16(uint32_t s, const void* g) {
    asm volatile("cp.async.cg.shared.global [%0], [%1], 16;" :: "r"(s), "l"(g));
}
__device__ __forceinline__ void cp_commit() {
    asm volatile("cp.async.commit_group;" ::: "memory");
}
template <int N> __device__ __forceinline__ void cp_wait() {
    asm volatile("cp.async.wait_group %0;" :: "n"(N) : "memory");
}
__device__ __forceinline__ void splith2(float2 v, uint32_t& h, uint32_t& l) {
    __half2 hh = __floats2half2_rn(v.x, v.y);
    h = *reinterpret_cast<uint32_t*>(&hh);
    float2 b = __half22float2(hh);
    __half2 ll = __floats2half2_rn(v.x - b.x, v.y - b.y);
    l = *reinterpret_cast<uint32_t*>(&ll);
}
__device__ __forceinline__ uint32_t h2pack(float a, float b) {
    __half2 h = __floats2half2_rn(a, b);
    return *reinterpret_cast<uint32_t*>(&h);
}

// ---------------------------------------------------------------------------
// weight conversion: fp32 -> fp16, all tensors in ONE launch (job table)
// ---------------------------------------------------------------------------
#define NJOBS 53
struct ConvJobs {
    const float* src[NJOBS];
    unsigned long long n[NJOBS];
    unsigned long long ofs[NJOBS];
};

__global__ void convert_w(ConvJobs jobs, __half* __restrict__ dst)
{
    const int jid = blockIdx.y;
    const float4* src = reinterpret_cast<const float4*>(jobs.src[jid]);
    uint4* d = reinterpret_cast<uint4*>(dst + jobs.ofs[jid]);
    const long long n8 = (long long)(jobs.n[jid] >> 3);
    const long long stride = (long long)gridDim.x * blockDim.x;
    for (long long i = blockIdx.x * (long long)blockDim.x + threadIdx.x; i < n8; i += stride) {
        float4 a = src[2 * i];
        float4 b = src[2 * i + 1];
        uint4 o;
        o.x = h2pack(a.x, a.y); o.y = h2pack(a.z, a.w);
        o.z = h2pack(b.x, b.y); o.w = h2pack(b.z, b.w);
        d[i] = o;
    }
}

__global__ void convert_pair(const float4* __restrict__ src,
                             uint2* __restrict__ h, uint2* __restrict__ l, int n4)
{
    const int stride = gridDim.x * blockDim.x;
    for (int i = blockIdx.x * blockDim.x + threadIdx.x; i < n4; i += stride) {
        float4 v = src[i];
        uint2 hh, ll;
        splith2(make_float2(v.x, v.y), hh.x, ll.x);
        splith2(make_float2(v.z, v.w), hh.y, ll.y);
        h[i] = hh;
        l[i] = ll;
    }
}

// ---------------------------------------------------------------------------
// GEMM: C[M,N] = A[M,K] @ W[N,K]^T. A = fp16 (h, optional l), B = fp16.
// CTA 128x128x32, 256 threads (8 warps: 4m x 2n), warp tile 32x64, 3 stages,
// 2 CTAs per SM. NPROD = 1 or 2 split products.
// ---------------------------------------------------------------------------
#define TM 128
#define TN 128
#define TK 32
#define GT 256
#define STAGES 3
#define ROWB 80
#define PARTB (128 * ROWB)       // 10240

#define EPI_NONE   0
#define EPI_BIAS   1
#define EPI_FF     2
#define EPI_ADD    3
#define EPI_CMIX   4

#define SMEM_NP2 (STAGES * 3 * PARTB)   // 92160
#define SMEM_NP1 (STAGES * 2 * PARTB)   // 61440

template <int EPI, int NPROD>
__global__ __launch_bounds__(GT, 2)
void gemm_f16(const __half* __restrict__ Ah, const __half* __restrict__ Al,
              const __half* __restrict__ Bh,
              float* __restrict__ C, int M, int N, int K,
              const float* __restrict__ bias,
              const float* __restrict__ Cin,
              const float* __restrict__ Rg,
              __half* __restrict__ Oh, int NSplit)
{
    constexpr int STAGE_SZ = (NPROD + 1) * PARTB;
    constexpr int OFF_AL = PARTB;                 // valid when NPROD==2
    constexpr int OFF_B  = NPROD * PARTB;

    extern __shared__ char smem[];
    const uint32_t sbase = smem_u32(smem);
    const int tid  = threadIdx.x;
    const int lane = tid & 31;
    const int wid  = tid >> 5;
    const int wm   = wid & 3;
    const int wn   = wid >> 2;
    const int bm   = blockIdx.y * TM;
    const int bn   = blockIdx.x * TN;

    const int lrow  = lane & 15;
    const int lchun = lane >> 4;

    float acc[2][8][4];
#pragma unroll
    for (int i = 0; i < 2; i++)
#pragma unroll
        for (int j = 0; j < 8; j++)
#pragma unroll
            for (int q = 0; q < 4; q++) acc[i][j][q] = 0.f;

    const int S = K / TK;

    auto issue = [&](int s, int buf) {
        const uint32_t sb = sbase + buf * STAGE_SZ;
        const int k0 = s * TK;
#pragma unroll
        for (int i = 0; i < 2; i++) {
            int idx = tid + i * GT;
            int row = idx >> 2, seg = idx & 3;
            uint32_t sa = sb + row * ROWB + seg * 16;
            size_t go = (size_t)(bm + row) * K + k0 + seg * 8;
            cp16(sa, Ah + go);
            if (NPROD == 2) cp16(sa + OFF_AL, Al + go);
        }
#pragma unroll
        for (int i = 0; i < 2; i++) {
            int idx = tid + i * GT;
            int row = idx >> 2, seg = idx & 3;
            uint32_t sa = sb + OFF_B + row * ROWB + seg * 16;
            size_t go = (size_t)(bn + row) * K + k0 + seg * 8;
            cp16(sa, Bh + go);
        }
        cp_commit();
    };

    issue(0, 0);
    issue(1, 1);

    for (int s = 0; s < S; s++) {
        const int buf = s % STAGES;
        cp_wait<1>();
        __syncthreads();

        const uint32_t sb = sbase + buf * STAGE_SZ;
#pragma unroll
        for (int kk = 0; kk < 2; kk++) {
            const uint32_t koff = (uint32_t)((kk * 2 + lchun) * 16);
            uint32_t ah[2][4], al[2][4];
#pragma unroll
            for (int mt = 0; mt < 2; mt++) {
                uint32_t aa = sb + (uint32_t)((wm * 32 + mt * 16 + lrow) * ROWB) + koff;
                ldm_x4(ah[mt], aa);
                if (NPROD == 2) ldm_x4(al[mt], aa + OFF_AL);
            }
#pragma unroll
            for (int bg = 0; bg < 2; bg++) {
                uint32_t bh[2][4];
#pragma unroll
                for (int bt = 0; bt < 2; bt++) {
                    uint32_t ba = sb + OFF_B +
                        (uint32_t)((wn * 64 + (bg * 2 + bt) * 16 + lrow) * ROWB) + koff;
                    ldm_x4(bh[bt], ba);
                }
#pragma unroll
                for (int mt = 0; mt < 2; mt++)
#pragma unroll
                    for (int bt = 0; bt < 2; bt++)
#pragma unroll
                        for (int j = 0; j < 2; j++)
                            mma_f16(acc[mt][bg * 4 + bt * 2 + j], ah[mt], bh[bt][j], bh[bt][2 + j]);
                if (NPROD == 2) {
#pragma unroll
                    for (int mt = 0; mt < 2; mt++)
#pragma unroll
                        for (int bt = 0; bt < 2; bt++)
#pragma unroll
                            for (int j = 0; j < 2; j++)
                                mma_f16(acc[mt][bg * 4 + bt * 2 + j], al[mt], bh[bt][j], bh[bt][2 + j]);
                }
            }
        }
        if (s + 2 < S) issue(s + 2, (s + 2) % STAGES);
    }

    // epilogue
#pragma unroll
    for (int mt = 0; mt < 2; mt++)
#pragma unroll
        for (int nt = 0; nt < 8; nt++) {
            const int row0 = bm + wm * 32 + mt * 16 + (lane >> 2);
            const int col  = bn + wn * 64 + (nt >> 1) * 16 + (nt & 1) * 8 + (lane & 3) * 2;
#pragma unroll
            for (int h = 0; h < 2; h++) {
                const int r = row0 + h * 8;
                float2 v = make_float2(acc[mt][nt][2 * h + 0], acc[mt][nt][2 * h + 1]);
                if (EPI == EPI_BIAS) {
                    float2 bb = *reinterpret_cast<const float2*>(bias + col);
                    v.x += bb.x; v.y += bb.y;
                    *reinterpret_cast<float2*>(C + (size_t)r * N + col) = v;
                }
                if (EPI == EPI_NONE) {
                    *reinterpret_cast<float2*>(C + (size_t)r * N + col) = v;
                }
                if (EPI == EPI_FF) {
                    if (col < NSplit) {
                        v.x = v.x > 0.f ? v.x * v.x : 0.f;
                        v.y = v.y > 0.f ? v.y * v.y : 0.f;
                        *reinterpret_cast<uint32_t*>(Oh + (size_t)r * NSplit + col) =
                            h2pack(v.x, v.y);
                    } else {
                        *reinterpret_cast<float2*>(C + (size_t)r * (N - NSplit) + col - NSplit) = v;
                    }
                }
                if (EPI == EPI_ADD) {
                    const size_t idx = (size_t)r * N + col;
                    float2 ci = *reinterpret_cast<const float2*>(Cin + idx);
                    v.x += ci.x; v.y += ci.y;
                    *reinterpret_cast<float2*>(C + idx) = v;
                }
                if (EPI == EPI_CMIX) {
                    const size_t idx = (size_t)r * N + col;
                    float2 ci = *reinterpret_cast<const float2*>(Cin + idx);
                    float2 rr = *reinterpret_cast<const float2*>(Rg + idx);
                    v.x = ci.x + v.x * (1.f / (1.f + expf(-rr.x)));
                    v.y = ci.y + v.y * (1.f / (1.f + expf(-rr.y)));
                    *reinterpret_cast<float2*>(C + idx) = v;
                }
            }
        }
}

// ---------------------------------------------------------------------------
// LayerNorm over E=1024; optional fp32 out and/or fp16 h/l out.
// ---------------------------------------------------------------------------
__global__ __launch_bounds__(256)
void ln_kernel(const float* __restrict__ x, float* __restrict__ o,
               __half* __restrict__ oh, __half* __restrict__ ol,
               const float* __restrict__ g, const float* __restrict__ b)
{
    __shared__ float sm[18];
    const int row = blockIdx.x;
    const int t   = threadIdx.x;
    float4 v = reinterpret_cast<const float4*>(x + (size_t)row * E_DIM)[t];
    float s  = v.x + v.y + v.z + v.w;
    float ss = v.x * v.x + v.y * v.y + v.z * v.z + v.w * v.w;
#pragma unroll
    for (int off = 16; off > 0; off >>= 1) {
        s  += __shfl_xor_sync(0xffffffffu, s, off);
        ss += __shfl_xor_sync(0xffffffffu, ss, off);
    }
    const int wp = t >> 5, lane = t & 31;
    if (lane == 0) { sm[wp] = s; sm[8 + wp] = ss; }
    __syncthreads();
    if (t < 32) {
        s  = (t < 8) ? sm[t]     : 0.f;
        ss = (t < 8) ? sm[8 + t] : 0.f;
#pragma unroll
        for (int off = 4; off > 0; off >>= 1) {
            s  += __shfl_xor_sync(0xffffffffu, s, off);
            ss += __shfl_xor_sync(0xffffffffu, ss, off);
        }
        if (t == 0) {
            float mean = s * (1.f / E_DIM);
            float var  = ss * (1.f / E_DIM) - mean * mean;
            sm[16] = mean;
            sm[17] = rsqrtf(var + 1e-5f);
        }
    }
    __syncthreads();
    const float mean = sm[16], inv = sm[17];
    float4 gg = reinterpret_cast<const float4*>(g)[t];
    float4 bb = reinterpret_cast<const float4*>(b)[t];
    float4 ov;
    ov.x = (v.x - mean) * inv * gg.x + bb.x;
    ov.y = (v.y - mean) * inv * gg.y + bb.y;
    ov.z = (v.z - mean) * inv * gg.z + bb.z;
    ov.w = (v.w - mean) * inv * gg.w + bb.w;
    if (o) reinterpret_cast<float4*>(o + (size_t)row * E_DIM)[t] = ov;
    if (oh) {
        uint2 hh, ll;
        splith2(make_float2(ov.x, ov.y), hh.x, ll.x);
        splith2(make_float2(ov.z, ov.w), hh.y, ll.y);
        reinterpret_cast<uint2*>(oh + (size_t)row * E_DIM)[t] = hh;
        reinterpret_cast<uint2*>(ol + (size_t)row * E_DIM)[t] = ll;
    }
}

// ---------------------------------------------------------------------------
// WKV recurrence, exact chunked 2-pass scan, reading the fused kr buffer
// (k at col e, v==r at col 1024+e, row stride 2048). pass2 emits fp16 yh.
// ---------------------------------------------------------------------------
__global__ __launch_bounds__(128)
void wkv_pass1(const float* __restrict__ kr,
               const float* __restrict__ decay, float* __restrict__ st)
{
    const int e = blockIdx.x * blockDim.x + threadIdx.x;
    const int c = blockIdx.y, b = blockIdx.z;
    const float w = -expf(decay[e]);
    float aa = 0.f, bb = 0.f, pp = -1e38f;
    const size_t base = ((size_t)b * T_LEN + (size_t)c * CHLEN) * 2048 + e;
    const float* kp = kr + base;
#pragma unroll 4
    for (int t = 0; t < CHLEN; t++) {
        float kt = kp[(size_t)t * 2048];
        float vt = kp[(size_t)t * 2048 + 1024];
        float ww = pp + w;
        float p  = fmaxf(ww, kt);
        float e1 = expf(ww - p);
        float e2 = expf(kt - p);
        aa = e1 * aa + e2 * vt;
        bb = e1 * bb + e2;
        pp = p;
    }
    float* s = st + ((size_t)(b * NCHUNK + c) * 3) * E_DIM + e;
    s[0] = aa; s[E_DIM] = bb; s[2 * E_DIM] = pp;
}

__global__ __launch_bounds__(128)
void wkv_pass2(const float* __restrict__ kr,
               const float* __restrict__ decay, const float* __restrict__ first,
               const float* __restrict__ st, __half* __restrict__ yh)
{
    const int e = blockIdx.x * blockDim.x + threadIdx.x;
    const int c = blockIdx.y, b = blockIdx.z;
    const float w = -expf(decay[e]);
    const float u = first[e];
    float aa = 0.f, bb = 0.f, pp = -1e38f;
    for (int j = 0; j < c; j++) {
        const float* s = st + ((size_t)(b * NCHUNK + j) * 3) * E_DIM + e;
        float pd = pp + (float)CHLEN * w;
        float a2 = s[0], b2 = s[E_DIM], p2 = s[2 * E_DIM];
        float p  = fmaxf(pd, p2);
        float e1 = expf(pd - p), e2 = expf(p2 - p);
        aa = e1 * aa + e2 * a2;
        bb = e1 * bb + e2 * b2;
        pp = p;
    }
    const size_t base = ((size_t)b * T_LEN + (size_t)c * CHLEN) * 2048 + e;
    const size_t ybase = ((size_t)b * T_LEN + (size_t)c * CHLEN) * E_DIM + e;
    const float* kp = kr + base;
    for (int t = 0; t < CHLEN; t++) {
        float kt = kp[(size_t)t * 2048];
        float vt = kp[(size_t)t * 2048 + 1024];   // v == r in this model
        float ww = u + kt;
        float p  = fmaxf(pp, ww);
        float e1 = expf(pp - p), e2 = expf(ww - p);
        float yt = (e1 * aa + e2 * vt) / (e1 * bb + e2);
        float ys = yt * (1.f / (1.f + expf(-vt)));
        yh[ybase + (size_t)t * E_DIM] = __float2half_rn(ys);
        float ww2 = pp + w;
        float p2  = fmaxf(ww2, kt);
        e1 = expf(ww2 - p2); e2 = expf(kt - p2);
        aa = e1 * aa + e2 * vt;
        bb = e1 * bb + e2;
        pp = p2;
    }
}

// ---------------------------------------------------------------------------
// Host orchestration
// ---------------------------------------------------------------------------
static void set_smem_attrs() {
    cudaFuncSetAttribute(gemm_f16<EPI_BIAS, 2>, cudaFuncAttributeMaxDynamicSharedMemorySize, SMEM_NP2);
    cudaFuncSetAttribute(gemm_f16<EPI_NONE, 2>, cudaFuncAttributeMaxDynamicSharedMemorySize, SMEM_NP2);
    cudaFuncSetAttribute(gemm_f16<EPI_FF,   2>, cudaFuncAttributeMaxDynamicSharedMemorySize, SMEM_NP2);
    cudaFuncSetAttribute(gemm_f16<EPI_ADD,  1>, cudaFuncAttributeMaxDynamicSharedMemorySize, SMEM_NP1);
    cudaFuncSetAttribute(gemm_f16<EPI_CMIX, 1>, cudaFuncAttributeMaxDynamicSharedMemorySize, SMEM_NP1);
}

extern "C" void kernel_launch(void* const* d_in, const int* in_sizes, int n_in,
                              void* d_out, int out_size)
{
    const float* inp    = (const float*)d_in[0];
    const float* W_in   = (const float*)d_in[1];
    const float* b_in   = (const float*)d_in[2];
    const float* ln0g   = (const float*)d_in[3];
    const float* ln0b   = (const float*)d_in[4];
    const float* l0ln1g = (const float*)d_in[5];
    const float* l0ln1b = (const float*)d_in[6];
    const float* l0ln2g = (const float*)d_in[7];
    const float* l0ln2b = (const float*)d_in[8];
    const float* l0cmk  = (const float*)d_in[9];
    const float* l0cmv  = (const float*)d_in[10];
    const float* l0cmr  = (const float*)d_in[11];
    const float* l0ffk  = (const float*)d_in[12];
    const float* l0ffv  = (const float*)d_in[13];
    const float* l0ffr  = (const float*)d_in[14];
    const float* tmk    = (const float*)d_in[15];
    const float* tmr    = (const float*)d_in[16];
    const float* tmo    = (const float*)d_in[17];
    const float* tmdec  = (const float*)d_in[18];
    const float* tmfst  = (const float*)d_in[19];
    const float* ln1g   = (const float*)d_in[20];
    const float* ln1b   = (const float*)d_in[21];
    const float* ln2g   = (const float*)d_in[22];
    const float* ln2b   = (const float*)d_in[23];
    const float* ffk    = (const float*)d_in[24];
    const float* ffv    = (const float*)d_in[25];
    const float* ffr    = (const float*)d_in[26];
    const float* outg   = (const float*)d_in[27];
    const float* outb   = (const float*)d_in[28];
    float* out = (float*)d_out;

    set_smem_attrs();

    __half *wf, *inh, *inl, *xnh, *xnl, *hbh, *yh;
    float *res, *tmp, *kr, *rb, *st;
    cudaGetSymbolAddress((void**)&wf,  g_wf);
    cudaGetSymbolAddress((void**)&inh, g_inh);
    cudaGetSymbolAddress((void**)&inl, g_inl);
    cudaGetSymbolAddress((void**)&xnh, g_xnh);
    cudaGetSymbolAddress((void**)&xnl, g_xnl);
    cudaGetSymbolAddress((void**)&hbh, g_hbh);
    cudaGetSymbolAddress((void**)&yh,  g_yh);
    cudaGetSymbolAddress((void**)&res, g_res);
    cudaGetSymbolAddress((void**)&tmp, g_tmp);
    cudaGetSymbolAddress((void**)&kr,  g_kr);
    cudaGetSymbolAddress((void**)&rb,  g_r);
    cudaGetSymbolAddress((void**)&st,  g_st);

    // ---- weight conversion: one job-table launch ----
    ConvJobs jobs;
    size_t off = 0;
    int ji = 0;
    auto addjob = [&](const float* src, size_t n, size_t dofs) {
        jobs.src[ji] = src;
        jobs.n[ji]   = (unsigned long long)n;
        jobs.ofs[ji] = (unsigned long long)dofs;
        ji++;
    };
    auto alloc = [&](size_t n) -> size_t { size_t o = off; off += n; return o; };

    const size_t o_win = alloc((size_t)E_DIM * D_IN);
    addjob(W_in, (size_t)E_DIM * D_IN, o_win);
    const size_t o_cm = alloc(FFL_);                 // l0 cmk (4096) + cmr (1024)
    addjob(l0cmk, FE_, o_cm);
    addjob(l0cmr, EE_, o_cm + FE_);
    const size_t o_cmv = alloc(FE_);
    addjob(l0cmv, FE_, o_cmv);
    const size_t o_lff = alloc(FFL_);                // l0 ffk + ffr
    addjob(l0ffk, FE_, o_lff);
    addjob(l0ffr, EE_, o_lff + FE_);
    const size_t o_lffv = alloc(FE_);
    addjob(l0ffv, FE_, o_lffv);
    const size_t o_kr = alloc((size_t)NLAYER * KRL_);
    for (int l = 0; l < NLAYER; l++) {
        addjob(tmk + (size_t)l * EE_, EE_, o_kr + (size_t)l * KRL_);
        addjob(tmr + (size_t)l * EE_, EE_, o_kr + (size_t)l * KRL_ + EE_);
    }
    const size_t o_tmo = alloc((size_t)NLAYER * EE_);
    addjob(tmo, (size_t)NLAYER * EE_, o_tmo);
    const size_t o_ff = alloc((size_t)NLAYER * FFL_);
    for (int l = 0; l < NLAYER; l++) {
        addjob(ffk + (size_t)l * FE_, FE_, o_ff + (size_t)l * FFL_);
        addjob(ffr + (size_t)l * EE_, EE_, o_ff + (size_t)l * FFL_ + FE_);
    }
    const size_t o_ffv = alloc((size_t)NLAYER * FE_);
    addjob(ffv, (size_t)NLAYER * FE_, o_ffv);

    convert_w<<<dim3(640, NJOBS), 256>>>(jobs, wf);
    convert_pair<<<1024, 256>>>((const float4*)inp, (uint2*)inh, (uint2*)inl,
                                (int)((size_t)BTOK * D_IN / 4));

    const dim3 gE   (E_DIM / TN,  BTOK / TM);   // (8, 32)
    const dim3 gKR  (2048 / TN,   BTOK / TM);   // (16, 32)
    const dim3 gFF  (5120 / TN,   BTOK / TM);   // (40, 32)
    const dim3 gWKV (E_DIM / 128, NCHUNK, BATCH);

    // x = inputs @ W_in^T + b_in ; res = LN(x, ln0)
    gemm_f16<EPI_BIAS, 2><<<gE, GT, SMEM_NP2>>>(inh, inl, wf + o_win,
        tmp, BTOK, E_DIM, D_IN, b_in, nullptr, nullptr, nullptr, 0);
    ln_kernel<<<BTOK, 256>>>(tmp, res, nullptr, nullptr, ln0g, ln0b);

    // channel mix (fused ffk+ffr GEMM, single-product ffv GEMM)
    auto cmix = [&](const float* lg, const float* lb, size_t okr_, size_t ov_) {
        ln_kernel<<<BTOK, 256>>>(res, nullptr, xnh, xnl, lg, lb);
        gemm_f16<EPI_FF, 2><<<gFF, GT, SMEM_NP2>>>(xnh, xnl, wf + okr_,
            rb, BTOK, 5120, E_DIM, nullptr, nullptr, nullptr, hbh, FOUR_E);
        gemm_f16<EPI_CMIX, 1><<<gE, GT, SMEM_NP1>>>(hbh, nullptr, wf + ov_,
            res, BTOK, E_DIM, FOUR_E, nullptr, res, rb, nullptr, 0);
    };

    cmix(l0ln1g, l0ln1b, o_cm,  o_cmv);
    cmix(l0ln2g, l0ln2b, o_lff, o_lffv);

    for (int l = 0; l < NLAYER; l++) {
        const size_t oE = (size_t)l * E_DIM;

        ln_kernel<<<BTOK, 256>>>(res, nullptr, xnh, xnl, ln1g + oE, ln1b + oE);
        gemm_f16<EPI_NONE, 2><<<gKR, GT, SMEM_NP2>>>(xnh, xnl, wf + o_kr + (size_t)l * KRL_,
            kr, BTOK, 2048, E_DIM, nullptr, nullptr, nullptr, nullptr, 0);
        wkv_pass1<<<gWKV, 128>>>(kr, tmdec + oE, st);
        wkv_pass2<<<gWKV, 128>>>(kr, tmdec + oE, tmfst + oE, st, yh);
        gemm_f16<EPI_ADD, 1><<<gE, GT, SMEM_NP1>>>(yh, nullptr, wf + o_tmo + (size_t)l * EE_,
            res, BTOK, E_DIM, E_DIM, nullptr, res, nullptr, nullptr, 0);

        ln_kernel<<<BTOK, 256>>>(res, nullptr, xnh, xnl, ln2g + oE, ln2b + oE);
        gemm_f16<EPI_FF, 2><<<gFF, GT, SMEM_NP2>>>(xnh, xnl, wf + o_ff + (size_t)l * FFL_,
            rb, BTOK, 5120, E_DIM, nullptr, nullptr, nullptr, hbh, FOUR_E);
        gemm_f16<EPI_CMIX, 1><<<gE, GT, SMEM_NP1>>>(hbh, nullptr, wf + o_ffv + (size_t)l * FE_,
            res, BTOK, E_DIM, FOUR_E, nullptr, res, rb, nullptr, 0);
    }

    ln_kernel<<<BTOK, 256>>>(res, out, nullptr, nullptr, outg, outb);
}

// round 10
// speedup vs baseline: 1.5731x; 1.2365x over previous
#include <cuda_runtime.h>
#include <cuda_fp16.h>
#include <cstdint>
#include <math.h>

// ---------------------------------------------------------------------------
// RWKV forward. GEMMs: mma.sync fp16. 2-product split (A=Ah+Al exact) only for
// the exp-sensitive kr GEMM and W_in; single-product everywhere else.
// k+r and ffk+ffr fused wide GEMMs. WKV = single fused kernel (smem states).
// ---------------------------------------------------------------------------

#define E_DIM   1024
#define FOUR_E  4096
#define D_IN    512
#define BTOK    4096
#define T_LEN   1024
#define BATCH   4
#define NLAYER  11
#define NCHUNK  16
#define CHLEN   64

#define EE_  1048576ull          // E*E
#define FE_  4194304ull          // 4E*E
#define KRL_ (2ull * EE_)        // fused k+r block per layer
#define FFL_ (FE_ + EE_)         // fused ffk+ffr block per layer

// ---------------- device-global scratch (no allocation allowed) ------------
#define WBUF_ELEMS 157810688ull
__device__ __half g_wf[WBUF_ELEMS];

__device__ __half g_inh[BTOK * D_IN],   g_inl[BTOK * D_IN];
__device__ __half g_xnh[BTOK * E_DIM],  g_xnl[BTOK * E_DIM];
__device__ __half g_hbh[BTOK * FOUR_E];
__device__ __half g_yh [BTOK * E_DIM];

__device__ float g_res[BTOK * E_DIM];
__device__ float g_tmp[BTOK * E_DIM];
__device__ float g_kr [BTOK * 2 * E_DIM];
__device__ float g_r  [BTOK * E_DIM];

// ---------------------------------------------------------------------------
// helpers
// ---------------------------------------------------------------------------
__device__ __forceinline__ uint32_t smem_u32(const void* p) {
    uint32_t a;
    asm("{ .reg .u64 t; cvta.to.shared.u64 t, %1; cvt.u32.u64 %0, t; }" : "=r"(a) : "l"(p));
    return a;
}
__device__ __forceinline__ void ldm_x4(uint32_t* r, uint32_t addr) {
    asm volatile("ldmatrix.sync.aligned.m8n8.x4.shared.b16 {%0,%1,%2,%3}, [%4];"
        : "=r"(r[0]), "=r"(r[1]), "=r"(r[2]), "=r"(r[3]) : "r"(addr));
}
__device__ __forceinline__ void mma_f16(float* d, const uint32_t* a, uint32_t b0, uint32_t b1) {
    asm volatile("mma.sync.aligned.m16n8k16.row.col.f32.f16.f16.f32 "
        "{%0,%1,%2,%3}, {%4,%5,%6,%7}, {%8,%9}, {%0,%1,%2,%3};"
        : "+f"(d[0]), "+f"(d[1]), "+f"(d[2]), "+f"(d[3])
        : "r"(a[0]), "r"(a[1]), "r"(a[2]), "r"(a[3]), "r"(b0), "r"(b1));
}
__device__ __forceinline__ void cp16(uint32_t s, const void* g) {
    asm volatile("cp.async.cg.shared.global [%0], [%1], 16;" :: "r"(s), "l"(g));
}
__device__ __forceinline__ void cp_commit() {
    asm volatile("cp.async.commit_group;" ::: "memory");
}
template <int N> __device__ __forceinline__ void cp_wait() {
    asm volatile("cp.async.wait_group %0;" :: "n"(N) : "memory");
}
__device__ __forceinline__ void splith2(float2 v, uint32_t& h, uint32_t& l) {
    __half2 hh = __floats2half2_rn(v.x, v.y);
    h = *reinterpret_cast<uint32_t*>(&hh);
    float2 b = __half22float2(hh);
    __half2 ll = __floats2half2_rn(v.x - b.x, v.y - b.y);
    l = *reinterpret_cast<uint32_t*>(&ll);
}
__device__ __forceinline__ uint32_t h2pack(float a, float b) {
    __half2 h = __floats2half2_rn(a, b);
    return *reinterpret_cast<uint32_t*>(&h);
}

// ---------------------------------------------------------------------------
// weight conversion: fp32 -> fp16, all tensors in ONE launch (job table)
// ---------------------------------------------------------------------------
#define NJOBS 53
struct ConvJobs {
    const float* src[NJOBS];
    unsigned long long n[NJOBS];
    unsigned long long ofs[NJOBS];
};

__global__ void convert_w(ConvJobs jobs, __half* __restrict__ dst)
{
    const int jid = blockIdx.y;
    const float4* src = reinterpret_cast<const float4*>(jobs.src[jid]);
    uint4* d = reinterpret_cast<uint4*>(dst + jobs.ofs[jid]);
    const long long n8 = (long long)(jobs.n[jid] >> 3);
    const long long stride = (long long)gridDim.x * blockDim.x;
    for (long long i = blockIdx.x * (long long)blockDim.x + threadIdx.x; i < n8; i += stride) {
        float4 a = src[2 * i];
        float4 b = src[2 * i + 1];
        uint4 o;
        o.x = h2pack(a.x, a.y); o.y = h2pack(a.z, a.w);
        o.z = h2pack(b.x, b.y); o.w = h2pack(b.z, b.w);
        d[i] = o;
    }
}

__global__ void convert_pair(const float4* __restrict__ src,
                             uint2* __restrict__ h, uint2* __restrict__ l, int n4)
{
    const int stride = gridDim.x * blockDim.x;
    for (int i = blockIdx.x * blockDim.x + threadIdx.x; i < n4; i += stride) {
        float4 v = src[i];
        uint2 hh, ll;
        splith2(make_float2(v.x, v.y), hh.x, ll.x);
        splith2(make_float2(v.z, v.w), hh.y, ll.y);
        h[i] = hh;
        l[i] = ll;
    }
}

// ---------------------------------------------------------------------------
// GEMM: C[M,N] = A[M,K] @ W[N,K]^T. A = fp16 (h, optional l), B = fp16.
// CTA 128x128x32, 256 threads (8 warps: 4m x 2n), warp tile 32x64, 3 stages,
// 2 CTAs per SM. NPROD = 1 or 2 split products.
// ---------------------------------------------------------------------------
#define TM 128
#define TN 128
#define TK 32
#define GT 256
#define STAGES 3
#define ROWB 80
#define PARTB (128 * ROWB)       // 10240

#define EPI_NONE   0
#define EPI_BIAS   1
#define EPI_FF     2
#define EPI_ADD    3
#define EPI_CMIX   4

#define SMEM_NP2 (STAGES * 3 * PARTB)   // 92160
#define SMEM_NP1 (STAGES * 2 * PARTB)   // 61440

template <int EPI, int NPROD>
__global__ __launch_bounds__(GT, 2)
void gemm_f16(const __half* __restrict__ Ah, const __half* __restrict__ Al,
              const __half* __restrict__ Bh,
              float* __restrict__ C, int M, int N, int K,
              const float* __restrict__ bias,
              const float* __restrict__ Cin,
              const float* __restrict__ Rg,
              __half* __restrict__ Oh, int NSplit)
{
    constexpr int STAGE_SZ = (NPROD + 1) * PARTB;
    constexpr int OFF_AL = PARTB;                 // valid when NPROD==2
    constexpr int OFF_B  = NPROD * PARTB;

    extern __shared__ char smem[];
    const uint32_t sbase = smem_u32(smem);
    const int tid  = threadIdx.x;
    const int lane = tid & 31;
    const int wid  = tid >> 5;
    const int wm   = wid & 3;
    const int wn   = wid >> 2;
    const int bm   = blockIdx.y * TM;
    const int bn   = blockIdx.x * TN;

    const int lrow  = lane & 15;
    const int lchun = lane >> 4;

    float acc[2][8][4];
#pragma unroll
    for (int i = 0; i < 2; i++)
#pragma unroll
        for (int j = 0; j < 8; j++)
#pragma unroll
            for (int q = 0; q < 4; q++) acc[i][j][q] = 0.f;

    const int S = K / TK;

    auto issue = [&](int s, int buf) {
        const uint32_t sb = sbase + buf * STAGE_SZ;
        const int k0 = s * TK;
#pragma unroll
        for (int i = 0; i < 2; i++) {
            int idx = tid + i * GT;
            int row = idx >> 2, seg = idx & 3;
            uint32_t sa = sb + row * ROWB + seg * 16;
            size_t go = (size_t)(bm + row) * K + k0 + seg * 8;
            cp16(sa, Ah + go);
            if (NPROD == 2) cp16(sa + OFF_AL, Al + go);
        }
#pragma unroll
        for (int i = 0; i < 2; i++) {
            int idx = tid + i * GT;
            int row = idx >> 2, seg = idx & 3;
            uint32_t sa = sb + OFF_B + row * ROWB + seg * 16;
            size_t go = (size_t)(bn + row) * K + k0 + seg * 8;
            cp16(sa, Bh + go);
        }
        cp_commit();
    };

    issue(0, 0);
    issue(1, 1);

    for (int s = 0; s < S; s++) {
        const int buf = s % STAGES;
        cp_wait<1>();
        __syncthreads();

        const uint32_t sb = sbase + buf * STAGE_SZ;
#pragma unroll
        for (int kk = 0; kk < 2; kk++) {
            const uint32_t koff = (uint32_t)((kk * 2 + lchun) * 16);
            uint32_t ah[2][4], al[2][4];
#pragma unroll
            for (int mt = 0; mt < 2; mt++) {
                uint32_t aa = sb + (uint32_t)((wm * 32 + mt * 16 + lrow) * ROWB) + koff;
                ldm_x4(ah[mt], aa);
                if (NPROD == 2) ldm_x4(al[mt], aa + OFF_AL);
            }
#pragma unroll
            for (int bg = 0; bg < 2; bg++) {
                uint32_t bh[2][4];
#pragma unroll
                for (int bt = 0; bt < 2; bt++) {
                    uint32_t ba = sb + OFF_B +
                        (uint32_t)((wn * 64 + (bg * 2 + bt) * 16 + lrow) * ROWB) + koff;
                    ldm_x4(bh[bt], ba);
                }
#pragma unroll
                for (int mt = 0; mt < 2; mt++)
#pragma unroll
                    for (int bt = 0; bt < 2; bt++)
#pragma unroll
                        for (int j = 0; j < 2; j++)
                            mma_f16(acc[mt][bg * 4 + bt * 2 + j], ah[mt], bh[bt][j], bh[bt][2 + j]);
                if (NPROD == 2) {
#pragma unroll
                    for (int mt = 0; mt < 2; mt++)
#pragma unroll
                        for (int bt = 0; bt < 2; bt++)
#pragma unroll
                            for (int j = 0; j < 2; j++)
                                mma_f16(acc[mt][bg * 4 + bt * 2 + j], al[mt], bh[bt][j], bh[bt][2 + j]);
                }
            }
        }
        if (s + 2 < S) issue(s + 2, (s + 2) % STAGES);
    }

    // epilogue
#pragma unroll
    for (int mt = 0; mt < 2; mt++)
#pragma unroll
        for (int nt = 0; nt < 8; nt++) {
            const int row0 = bm + wm * 32 + mt * 16 + (lane >> 2);
            const int col  = bn + wn * 64 + (nt >> 1) * 16 + (nt & 1) * 8 + (lane & 3) * 2;
#pragma unroll
            for (int h = 0; h < 2; h++) {
                const int r = row0 + h * 8;
                float2 v = make_float2(acc[mt][nt][2 * h + 0], acc[mt][nt][2 * h + 1]);
                if (EPI == EPI_BIAS) {
                    float2 bb = *reinterpret_cast<const float2*>(bias + col);
                    v.x += bb.x; v.y += bb.y;
                    *reinterpret_cast<float2*>(C + (size_t)r * N + col) = v;
                }
                if (EPI == EPI_NONE) {
                    *reinterpret_cast<float2*>(C + (size_t)r * N + col) = v;
                }
                if (EPI == EPI_FF) {
                    if (col < NSplit) {
                        v.x = v.x > 0.f ? v.x * v.x : 0.f;
                        v.y = v.y > 0.f ? v.y * v.y : 0.f;
                        *reinterpret_cast<uint32_t*>(Oh + (size_t)r * NSplit + col) =
                            h2pack(v.x, v.y);
                    } else {
                        *reinterpret_cast<float2*>(C + (size_t)r * (N - NSplit) + col - NSplit) = v;
                    }
                }
                if (EPI == EPI_ADD) {
                    const size_t idx = (size_t)r * N + col;
                    float2 ci = *reinterpret_cast<const float2*>(Cin + idx);
                    v.x += ci.x; v.y += ci.y;
                    *reinterpret_cast<float2*>(C + idx) = v;
                }
                if (EPI == EPI_CMIX) {
                    const size_t idx = (size_t)r * N + col;
                    float2 ci = *reinterpret_cast<const float2*>(Cin + idx);
                    float2 rr = *reinterpret_cast<const float2*>(Rg + idx);
                    v.x = ci.x + v.x * (1.f / (1.f + expf(-rr.x)));
                    v.y = ci.y + v.y * (1.f / (1.f + expf(-rr.y)));
                    *reinterpret_cast<float2*>(C + idx) = v;
                }
            }
        }
}

// ---------------------------------------------------------------------------
// LayerNorm over E=1024; optional fp32 out, fp16 hi out, fp16 lo out.
// ---------------------------------------------------------------------------
__global__ __launch_bounds__(256)
void ln_kernel(const float* __restrict__ x, float* __restrict__ o,
               __half* __restrict__ oh, __half* __restrict__ ol,
               const float* __restrict__ g, const float* __restrict__ b)
{
    __shared__ float sm[18];
    const int row = blockIdx.x;
    const int t   = threadIdx.x;
    float4 v = reinterpret_cast<const float4*>(x + (size_t)row * E_DIM)[t];
    float s  = v.x + v.y + v.z + v.w;
    float ss = v.x * v.x + v.y * v.y + v.z * v.z + v.w * v.w;
#pragma unroll
    for (int off = 16; off > 0; off >>= 1) {
        s  += __shfl_xor_sync(0xffffffffu, s, off);
        ss += __shfl_xor_sync(0xffffffffu, ss, off);
    }
    const int wp = t >> 5, lane = t & 31;
    if (lane == 0) { sm[wp] = s; sm[8 + wp] = ss; }
    __syncthreads();
    if (t < 32) {
        s  = (t < 8) ? sm[t]     : 0.f;
        ss = (t < 8) ? sm[8 + t] : 0.f;
#pragma unroll
        for (int off = 4; off > 0; off >>= 1) {
            s  += __shfl_xor_sync(0xffffffffu, s, off);
            ss += __shfl_xor_sync(0xffffffffu, ss, off);
        }
        if (t == 0) {
            float mean = s * (1.f / E_DIM);
            float var  = ss * (1.f / E_DIM) - mean * mean;
            sm[16] = mean;
            sm[17] = rsqrtf(var + 1e-5f);
        }
    }
    __syncthreads();
    const float mean = sm[16], inv = sm[17];
    float4 gg = reinterpret_cast<const float4*>(g)[t];
    float4 bb = reinterpret_cast<const float4*>(b)[t];
    float4 ov;
    ov.x = (v.x - mean) * inv * gg.x + bb.x;
    ov.y = (v.y - mean) * inv * gg.y + bb.y;
    ov.z = (v.z - mean) * inv * gg.z + bb.z;
    ov.w = (v.w - mean) * inv * gg.w + bb.w;
    if (o) reinterpret_cast<float4*>(o + (size_t)row * E_DIM)[t] = ov;
    if (oh) {
        uint2 hh, ll;
        splith2(make_float2(ov.x, ov.y), hh.x, ll.x);
        splith2(make_float2(ov.z, ov.w), hh.y, ll.y);
        reinterpret_cast<uint2*>(oh + (size_t)row * E_DIM)[t] = hh;
        if (ol) reinterpret_cast<uint2*>(ol + (size_t)row * E_DIM)[t] = ll;
    }
}

// ---------------------------------------------------------------------------
// WKV recurrence, fused single kernel. Block = 512 threads = 32 channels x 16
// chunks; chunk states in smem; warp-uniform prefix; replay emits fp16 yh.
// kr layout: k at col e, v==r at col 1024+e, row stride 2048.
// ---------------------------------------------------------------------------
__global__ __launch_bounds__(512)
void wkv_fused(const float* __restrict__ kr,
               const float* __restrict__ decay, const float* __restrict__ first,
               __half* __restrict__ yh)
{
    __shared__ float s_a[NCHUNK][32], s_b[NCHUNK][32], s_p[NCHUNK][32];
    const int ch = threadIdx.x & 31;
    const int c  = threadIdx.x >> 5;          // chunk, warp-uniform
    const int e  = blockIdx.x * 32 + ch;
    const int b  = blockIdx.y;
    const float w = -expf(decay[e]);
    const float u = first[e];

    const size_t base  = ((size_t)b * T_LEN + (size_t)c * CHLEN) * 2048 + e;
    const size_t ybase = ((size_t)b * T_LEN + (size_t)c * CHLEN) * E_DIM + e;
    const float* kp = kr + base;

    // pass 1: chunk-local scan from zero state
    float aa = 0.f, bb = 0.f, pp = -1e38f;
#pragma unroll 4
    for (int t = 0; t < CHLEN; t++) {
        float kt = kp[(size_t)t * 2048];
        float vt = kp[(size_t)t * 2048 + 1024];
        float ww = pp + w;
        float p  = fmaxf(ww, kt);
        float e1 = expf(ww - p), e2 = expf(kt - p);
        aa = e1 * aa + e2 * vt;
        bb = e1 * bb + e2;
        pp = p;
    }
    s_a[c][ch] = aa; s_b[c][ch] = bb; s_p[c][ch] = pp;
    __syncthreads();

    // prefix over previous chunks (<=15 iters, warp-uniform trip count)
    aa = 0.f; bb = 0.f; pp = -1e38f;
    for (int j = 0; j < c; j++) {
        float pd = pp + (float)CHLEN * w;
        float a2 = s_a[j][ch], b2 = s_b[j][ch], p2 = s_p[j][ch];
        float p  = fmaxf(pd, p2);
        float e1 = expf(pd - p), e2 = expf(p2 - p);
        aa = e1 * aa + e2 * a2;
        bb = e1 * bb + e2 * b2;
        pp = p;
    }

    // replay emitting y = sigmoid(r) * wkv  (v == r)
    for (int t = 0; t < CHLEN; t++) {
        float kt = kp[(size_t)t * 2048];
        float vt = kp[(size_t)t * 2048 + 1024];
        float ww = u + kt;
        float p  = fmaxf(pp, ww);
        float e1 = expf(pp - p), e2 = expf(ww - p);
        float yt = (e1 * aa + e2 * vt) / (e1 * bb + e2);
        float ys = yt * (1.f / (1.f + expf(-vt)));
        yh[ybase + (size_t)t * E_DIM] = __float2half_rn(ys);
        float ww2 = pp + w;
        float p2  = fmaxf(ww2, kt);
        e1 = expf(ww2 - p2); e2 = expf(kt - p2);
        aa = e1 * aa + e2 * vt;
        bb = e1 * bb + e2;
        pp = p2;
    }
}

// ---------------------------------------------------------------------------
// Host orchestration
// ---------------------------------------------------------------------------
static void set_smem_attrs() {
    cudaFuncSetAttribute(gemm_f16<EPI_BIAS, 2>, cudaFuncAttributeMaxDynamicSharedMemorySize, SMEM_NP2);
    cudaFuncSetAttribute(gemm_f16<EPI_NONE, 2>, cudaFuncAttributeMaxDynamicSharedMemorySize, SMEM_NP2);
    cudaFuncSetAttribute(gemm_f16<EPI_FF,   1>, cudaFuncAttributeMaxDynamicSharedMemorySize, SMEM_NP1);
    cudaFuncSetAttribute(gemm_f16<EPI_ADD,  1>, cudaFuncAttributeMaxDynamicSharedMemorySize, SMEM_NP1);
    cudaFuncSetAttribute(gemm_f16<EPI_CMIX, 1>, cudaFuncAttributeMaxDynamicSharedMemorySize, SMEM_NP1);
}

extern "C" void kernel_launch(void* const* d_in, const int* in_sizes, int n_in,
                              void* d_out, int out_size)
{
    const float* inp    = (const float*)d_in[0];
    const float* W_in   = (const float*)d_in[1];
    const float* b_in   = (const float*)d_in[2];
    const float* ln0g   = (const float*)d_in[3];
    const float* ln0b   = (const float*)d_in[4];
    const float* l0ln1g = (const float*)d_in[5];
    const float* l0ln1b = (const float*)d_in[6];
    const float* l0ln2g = (const float*)d_in[7];
    const float* l0ln2b = (const float*)d_in[8];
    const float* l0cmk  = (const float*)d_in[9];
    const float* l0cmv  = (const float*)d_in[10];
    const float* l0cmr  = (const float*)d_in[11];
    const float* l0ffk  = (const float*)d_in[12];
    const float* l0ffv  = (const float*)d_in[13];
    const float* l0ffr  = (const float*)d_in[14];
    const float* tmk    = (const float*)d_in[15];
    const float* tmr    = (const float*)d_in[16];
    const float* tmo    = (const float*)d_in[17];
    const float* tmdec  = (const float*)d_in[18];
    const float* tmfst  = (const float*)d_in[19];
    const float* ln1g   = (const float*)d_in[20];
    const float* ln1b   = (const float*)d_in[21];
    const float* ln2g   = (const float*)d_in[22];
    const float* ln2b   = (const float*)d_in[23];
    const float* ffk    = (const float*)d_in[24];
    const float* ffv    = (const float*)d_in[25];
    const float* ffr    = (const float*)d_in[26];
    const float* outg   = (const float*)d_in[27];
    const float* outb   = (const float*)d_in[28];
    float* out = (float*)d_out;

    set_smem_attrs();

    __half *wf, *inh, *inl, *xnh, *xnl, *hbh, *yh;
    float *res, *tmp, *kr, *rb;
    cudaGetSymbolAddress((void**)&wf,  g_wf);
    cudaGetSymbolAddress((void**)&inh, g_inh);
    cudaGetSymbolAddress((void**)&inl, g_inl);
    cudaGetSymbolAddress((void**)&xnh, g_xnh);
    cudaGetSymbolAddress((void**)&xnl, g_xnl);
    cudaGetSymbolAddress((void**)&hbh, g_hbh);
    cudaGetSymbolAddress((void**)&yh,  g_yh);
    cudaGetSymbolAddress((void**)&res, g_res);
    cudaGetSymbolAddress((void**)&tmp, g_tmp);
    cudaGetSymbolAddress((void**)&kr,  g_kr);
    cudaGetSymbolAddress((void**)&rb,  g_r);

    // ---- weight conversion: one job-table launch ----
    ConvJobs jobs;
    size_t off = 0;
    int ji = 0;
    auto addjob = [&](const float* src, size_t n, size_t dofs) {
        jobs.src[ji] = src;
        jobs.n[ji]   = (unsigned long long)n;
        jobs.ofs[ji] = (unsigned long long)dofs;
        ji++;
    };
    auto alloc = [&](size_t n) -> size_t { size_t o = off; off += n; return o; };

    const size_t o_win = alloc((size_t)E_DIM * D_IN);
    addjob(W_in, (size_t)E_DIM * D_IN, o_win);
    const size_t o_cm = alloc(FFL_);                 // l0 cmk (4096) + cmr (1024)
    addjob(l0cmk, FE_, o_cm);
    addjob(l0cmr, EE_, o_cm + FE_);
    const size_t o_cmv = alloc(FE_);
    addjob(l0cmv, FE_, o_cmv);
    const size_t o_lff = alloc(FFL_);                // l0 ffk + ffr
    addjob(l0ffk, FE_, o_lff);
    addjob(l0ffr, EE_, o_lff + FE_);
    const size_t o_lffv = alloc(FE_);
    addjob(l0ffv, FE_, o_lffv);
    const size_t o_kr = alloc((size_t)NLAYER * KRL_);
    for (int l = 0; l < NLAYER; l++) {
        addjob(tmk + (size_t)l * EE_, EE_, o_kr + (size_t)l * KRL_);
        addjob(tmr + (size_t)l * EE_, EE_, o_kr + (size_t)l * KRL_ + EE_);
    }
    const size_t o_tmo = alloc((size_t)NLAYER * EE_);
    addjob(tmo, (size_t)NLAYER * EE_, o_tmo);
    const size_t o_ff = alloc((size_t)NLAYER * FFL_);
    for (int l = 0; l < NLAYER; l++) {
        addjob(ffk + (size_t)l * FE_, FE_, o_ff + (size_t)l * FFL_);
        addjob(ffr + (size_t)l * EE_, EE_, o_ff + (size_t)l * FFL_ + FE_);
    }
    const size_t o_ffv = alloc((size_t)NLAYER * FE_);
    addjob(ffv, (size_t)NLAYER * FE_, o_ffv);

    convert_w<<<dim3(640, NJOBS), 256>>>(jobs, wf);
    convert_pair<<<1024, 256>>>((const float4*)inp, (uint2*)inh, (uint2*)inl,
                                (int)((size_t)BTOK * D_IN / 4));

    const dim3 gE   (E_DIM / TN,  BTOK / TM);   // (8, 32)
    const dim3 gKR  (2048 / TN,   BTOK / TM);   // (16, 32)
    const dim3 gFF  (5120 / TN,   BTOK / TM);   // (40, 32)
    const dim3 gWKV (E_DIM / 32,  BATCH);       // (32, 4) = 128 CTAs x 512 thr

    // x = inputs @ W_in^T + b_in ; res = LN(x, ln0)
    gemm_f16<EPI_BIAS, 2><<<gE, GT, SMEM_NP2>>>(inh, inl, wf + o_win,
        tmp, BTOK, E_DIM, D_IN, b_in, nullptr, nullptr, nullptr, 0);
    ln_kernel<<<BTOK, 256>>>(tmp, res, nullptr, nullptr, ln0g, ln0b);

    // channel mix (fused ffk+ffr GEMM 1-prod, ffv GEMM 1-prod)
    auto cmix = [&](const float* lg, const float* lb, size_t okr_, size_t ov_) {
        ln_kernel<<<BTOK, 256>>>(res, nullptr, xnh, nullptr, lg, lb);
        gemm_f16<EPI_FF, 1><<<gFF, GT, SMEM_NP1>>>(xnh, nullptr, wf + okr_,
            rb, BTOK, 5120, E_DIM, nullptr, nullptr, nullptr, hbh, FOUR_E);
        gemm_f16<EPI_CMIX, 1><<<gE, GT, SMEM_NP1>>>(hbh, nullptr, wf + ov_,
            res, BTOK, E_DIM, FOUR_E, nullptr, res, rb, nullptr, 0);
    };

    cmix(l0ln1g, l0ln1b, o_cm,  o_cmv);
    cmix(l0ln2g, l0ln2b, o_lff, o_lffv);

    for (int l = 0; l < NLAYER; l++) {
        const size_t oE = (size_t)l * E_DIM;

        ln_kernel<<<BTOK, 256>>>(res, nullptr, xnh, xnl, ln1g + oE, ln1b + oE);
        gemm_f16<EPI_NONE, 2><<<gKR, GT, SMEM_NP2>>>(xnh, xnl, wf + o_kr + (size_t)l * KRL_,
            kr, BTOK, 2048, E_DIM, nullptr, nullptr, nullptr, nullptr, 0);
        wkv_fused<<<gWKV, 512>>>(kr, tmdec + oE, tmfst + oE, yh);
        gemm_f16<EPI_ADD, 1><<<gE, GT, SMEM_NP1>>>(yh, nullptr, wf + o_tmo + (size_t)l * EE_,
            res, BTOK, E_DIM, E_DIM, nullptr, res, nullptr, nullptr, 0);

        ln_kernel<<<BTOK, 256>>>(res, nullptr, xnh, nullptr, ln2g + oE, ln2b + oE);
        gemm_f16<EPI_FF, 1><<<gFF, GT, SMEM_NP1>>>(xnh, nullptr, wf + o_ff + (size_t)l * FFL_,
            rb, BTOK, 5120, E_DIM, nullptr, nullptr, nullptr, hbh, FOUR_E);
        gemm_f16<EPI_CMIX, 1><<<gE, GT, SMEM_NP1>>>(hbh, nullptr, wf + o_ffv + (size_t)l * FE_,
            res, BTOK, E_DIM, FOUR_E, nullptr, res, rb, nullptr, 0);
    }

    ln_kernel<<<BTOK, 256>>>(res, out, nullptr, nullptr, outg, outb);
}

// round 11
// speedup vs baseline: 1.7325x; 1.1013x over previous
#include <cuda_runtime.h>
#include <cuda_fp16.h>
#include <cstdint>
#include <math.h>

// ---------------------------------------------------------------------------
// RWKV forward. GEMMs: mma.sync fp16, single-product everywhere except the
// tiny W_in GEMM (2-product). k+r and ffk+ffr fused wide GEMMs. WKV = single
// fused kernel (chunked scan, smem states).
// ---------------------------------------------------------------------------

#define E_DIM   1024
#define FOUR_E  4096
#define D_IN    512
#define BTOK    4096
#define T_LEN   1024
#define BATCH   4
#define NLAYER  11
#define NCHUNK  16
#define CHLEN   64

#define EE_  1048576ull          // E*E
#define FE_  4194304ull          // 4E*E
#define KRL_ (2ull * EE_)        // fused k+r block per layer
#define FFL_ (FE_ + EE_)         // fused ffk+ffr block per layer

// ---------------- device-global scratch (no allocation allowed) ------------
#define WBUF_ELEMS 157810688ull
__device__ __half g_wf[WBUF_ELEMS];

__device__ __half g_inh[BTOK * D_IN],   g_inl[BTOK * D_IN];
__device__ __half g_xnh[BTOK * E_DIM];
__device__ __half g_hbh[BTOK * FOUR_E];
__device__ __half g_yh [BTOK * E_DIM];

__device__ float g_res[BTOK * E_DIM];
__device__ float g_tmp[BTOK * E_DIM];
__device__ float g_kr [BTOK * 2 * E_DIM];
__device__ float g_r  [BTOK * E_DIM];

// ---------------------------------------------------------------------------
// helpers
// ---------------------------------------------------------------------------
__device__ __forceinline__ uint32_t smem_u32(const void* p) {
    uint32_t a;
    asm("{ .reg .u64 t; cvta.to.shared.u64 t, %1; cvt.u32.u64 %0, t; }" : "=r"(a) : "l"(p));
    return a;
}
__device__ __forceinline__ void ldm_x4(uint32_t* r, uint32_t addr) {
    asm volatile("ldmatrix.sync.aligned.m8n8.x4.shared.b16 {%0,%1,%2,%3}, [%4];"
        : "=r"(r[0]), "=r"(r[1]), "=r"(r[2]), "=r"(r[3]) : "r"(addr));
}
__device__ __forceinline__ void mma_f16(float* d, const uint32_t* a, uint32_t b0, uint32_t b1) {
    asm volatile("mma.sync.aligned.m16n8k16.row.col.f32.f16.f16.f32 "
        "{%0,%1,%2,%3}, {%4,%5,%6,%7}, {%8,%9}, {%0,%1,%2,%3};"
        : "+f"(d[0]), "+f"(d[1]), "+f"(d[2]), "+f"(d[3])
        : "r"(a[0]), "r"(a[1]), "r"(a[2]), "r"(a[3]), "r"(b0), "r"(b1));
}
__device__ __forceinline__ void cp16(uint32_t s, const void* g) {
    asm volatile("cp.async.cg.shared.global [%0], [%1], 16;" :: "r"(s), "l"(g));
}
__device__ __forceinline__ void cp_commit() {
    asm volatile("cp.async.commit_group;" ::: "memory");
}
template <int N> __device__ __forceinline__ void cp_wait() {
    asm volatile("cp.async.wait_group %0;" :: "n"(N) : "memory");
}
__device__ __forceinline__ void splith2(float2 v, uint32_t& h, uint32_t& l) {
    __half2 hh = __floats2half2_rn(v.x, v.y);
    h = *reinterpret_cast<uint32_t*>(&hh);
    float2 b = __half22float2(hh);
    __half2 ll = __floats2half2_rn(v.x - b.x, v.y - b.y);
    l = *reinterpret_cast<uint32_t*>(&ll);
}
__device__ __forceinline__ uint32_t h2pack(float a, float b) {
    __half2 h = __floats2half2_rn(a, b);
    return *reinterpret_cast<uint32_t*>(&h);
}

// ---------------------------------------------------------------------------
// weight conversion: fp32 -> fp16, all tensors in ONE launch (job table)
// ---------------------------------------------------------------------------
#define NJOBS 53
struct ConvJobs {
    const float* src[NJOBS];
    unsigned long long n[NJOBS];
    unsigned long long ofs[NJOBS];
};

__global__ void convert_w(ConvJobs jobs, __half* __restrict__ dst)
{
    const int jid = blockIdx.y;
    const float4* src = reinterpret_cast<const float4*>(jobs.src[jid]);
    uint4* d = reinterpret_cast<uint4*>(dst + jobs.ofs[jid]);
    const long long n8 = (long long)(jobs.n[jid] >> 3);
    const long long stride = (long long)gridDim.x * blockDim.x;
    for (long long i = blockIdx.x * (long long)blockDim.x + threadIdx.x; i < n8; i += stride) {
        float4 a = src[2 * i];
        float4 b = src[2 * i + 1];
        uint4 o;
        o.x = h2pack(a.x, a.y); o.y = h2pack(a.z, a.w);
        o.z = h2pack(b.x, b.y); o.w = h2pack(b.z, b.w);
        d[i] = o;
    }
}

__global__ void convert_pair(const float4* __restrict__ src,
                             uint2* __restrict__ h, uint2* __restrict__ l, int n4)
{
    const int stride = gridDim.x * blockDim.x;
    for (int i = blockIdx.x * blockDim.x + threadIdx.x; i < n4; i += stride) {
        float4 v = src[i];
        uint2 hh, ll;
        splith2(make_float2(v.x, v.y), hh.x, ll.x);
        splith2(make_float2(v.z, v.w), hh.y, ll.y);
        h[i] = hh;
        l[i] = ll;
    }
}

// ---------------------------------------------------------------------------
// GEMM: C[M,N] = A[M,K] @ W[N,K]^T. A = fp16 (h, optional l), B = fp16.
// CTA 128x128x32, 256 threads (8 warps: 4m x 2n), warp tile 32x64, 3 stages,
// 2 CTAs per SM. NPROD = 1 or 2 split products.
// ---------------------------------------------------------------------------
#define TM 128
#define TN 128
#define TK 32
#define GT 256
#define STAGES 3
#define ROWB 80
#define PARTB (128 * ROWB)       // 10240

#define EPI_NONE   0
#define EPI_BIAS   1
#define EPI_FF     2
#define EPI_ADD    3
#define EPI_CMIX   4

#define SMEM_NP2 (STAGES * 3 * PARTB)   // 92160
#define SMEM_NP1 (STAGES * 2 * PARTB)   // 61440

template <int EPI, int NPROD>
__global__ __launch_bounds__(GT, 2)
void gemm_f16(const __half* __restrict__ Ah, const __half* __restrict__ Al,
              const __half* __restrict__ Bh,
              float* __restrict__ C, int M, int N, int K,
              const float* __restrict__ bias,
              const float* __restrict__ Cin,
              const float* __restrict__ Rg,
              __half* __restrict__ Oh, int NSplit)
{
    constexpr int STAGE_SZ = (NPROD + 1) * PARTB;
    constexpr int OFF_AL = PARTB;                 // valid when NPROD==2
    constexpr int OFF_B  = NPROD * PARTB;

    extern __shared__ char smem[];
    const uint32_t sbase = smem_u32(smem);
    const int tid  = threadIdx.x;
    const int lane = tid & 31;
    const int wid  = tid >> 5;
    const int wm   = wid & 3;
    const int wn   = wid >> 2;
    const int bm   = blockIdx.y * TM;
    const int bn   = blockIdx.x * TN;

    const int lrow  = lane & 15;
    const int lchun = lane >> 4;

    float acc[2][8][4];
#pragma unroll
    for (int i = 0; i < 2; i++)
#pragma unroll
        for (int j = 0; j < 8; j++)
#pragma unroll
            for (int q = 0; q < 4; q++) acc[i][j][q] = 0.f;

    const int S = K / TK;

    auto issue = [&](int s, int buf) {
        const uint32_t sb = sbase + buf * STAGE_SZ;
        const int k0 = s * TK;
#pragma unroll
        for (int i = 0; i < 2; i++) {
            int idx = tid + i * GT;
            int row = idx >> 2, seg = idx & 3;
            uint32_t sa = sb + row * ROWB + seg * 16;
            size_t go = (size_t)(bm + row) * K + k0 + seg * 8;
            cp16(sa, Ah + go);
            if (NPROD == 2) cp16(sa + OFF_AL, Al + go);
        }
#pragma unroll
        for (int i = 0; i < 2; i++) {
            int idx = tid + i * GT;
            int row = idx >> 2, seg = idx & 3;
            uint32_t sa = sb + OFF_B + row * ROWB + seg * 16;
            size_t go = (size_t)(bn + row) * K + k0 + seg * 8;
            cp16(sa, Bh + go);
        }
        cp_commit();
    };

    issue(0, 0);
    issue(1, 1);

    for (int s = 0; s < S; s++) {
        const int buf = s % STAGES;
        cp_wait<1>();
        __syncthreads();

        const uint32_t sb = sbase + buf * STAGE_SZ;
#pragma unroll
        for (int kk = 0; kk < 2; kk++) {
            const uint32_t koff = (uint32_t)((kk * 2 + lchun) * 16);
            uint32_t ah[2][4], al[2][4];
#pragma unroll
            for (int mt = 0; mt < 2; mt++) {
                uint32_t aa = sb + (uint32_t)((wm * 32 + mt * 16 + lrow) * ROWB) + koff;
                ldm_x4(ah[mt], aa);
                if (NPROD == 2) ldm_x4(al[mt], aa + OFF_AL);
            }
#pragma unroll
            for (int bg = 0; bg < 2; bg++) {
                uint32_t bh[2][4];
#pragma unroll
                for (int bt = 0; bt < 2; bt++) {
                    uint32_t ba = sb + OFF_B +
                        (uint32_t)((wn * 64 + (bg * 2 + bt) * 16 + lrow) * ROWB) + koff;
                    ldm_x4(bh[bt], ba);
                }
#pragma unroll
                for (int mt = 0; mt < 2; mt++)
#pragma unroll
                    for (int bt = 0; bt < 2; bt++)
#pragma unroll
                        for (int j = 0; j < 2; j++)
                            mma_f16(acc[mt][bg * 4 + bt * 2 + j], ah[mt], bh[bt][j], bh[bt][2 + j]);
                if (NPROD == 2) {
#pragma unroll
                    for (int mt = 0; mt < 2; mt++)
#pragma unroll
                        for (int bt = 0; bt < 2; bt++)
#pragma unroll
                            for (int j = 0; j < 2; j++)
                                mma_f16(acc[mt][bg * 4 + bt * 2 + j], al[mt], bh[bt][j], bh[bt][2 + j]);
                }
            }
        }
        if (s + 2 < S) issue(s + 2, (s + 2) % STAGES);
    }

    // epilogue
#pragma unroll
    for (int mt = 0; mt < 2; mt++)
#pragma unroll
        for (int nt = 0; nt < 8; nt++) {
            const int row0 = bm + wm * 32 + mt * 16 + (lane >> 2);
            const int col  = bn + wn * 64 + (nt >> 1) * 16 + (nt & 1) * 8 + (lane & 3) * 2;
#pragma unroll
            for (int h = 0; h < 2; h++) {
                const int r = row0 + h * 8;
                float2 v = make_float2(acc[mt][nt][2 * h + 0], acc[mt][nt][2 * h + 1]);
                if (EPI == EPI_BIAS) {
                    float2 bb = *reinterpret_cast<const float2*>(bias + col);
                    v.x += bb.x; v.y += bb.y;
                    *reinterpret_cast<float2*>(C + (size_t)r * N + col) = v;
                }
                if (EPI == EPI_NONE) {
                    *reinterpret_cast<float2*>(C + (size_t)r * N + col) = v;
                }
                if (EPI == EPI_FF) {
                    if (col < NSplit) {
                        v.x = v.x > 0.f ? v.x * v.x : 0.f;
                        v.y = v.y > 0.f ? v.y * v.y : 0.f;
                        *reinterpret_cast<uint32_t*>(Oh + (size_t)r * NSplit + col) =
                            h2pack(v.x, v.y);
                    } else {
                        *reinterpret_cast<float2*>(C + (size_t)r * (N - NSplit) + col - NSplit) = v;
                    }
                }
                if (EPI == EPI_ADD) {
                    const size_t idx = (size_t)r * N + col;
                    float2 ci = *reinterpret_cast<const float2*>(Cin + idx);
                    v.x += ci.x; v.y += ci.y;
                    *reinterpret_cast<float2*>(C + idx) = v;
                }
                if (EPI == EPI_CMIX) {
                    const size_t idx = (size_t)r * N + col;
                    float2 ci = *reinterpret_cast<const float2*>(Cin + idx);
                    float2 rr = *reinterpret_cast<const float2*>(Rg + idx);
                    v.x = ci.x + v.x * (1.f / (1.f + expf(-rr.x)));
                    v.y = ci.y + v.y * (1.f / (1.f + expf(-rr.y)));
                    *reinterpret_cast<float2*>(C + idx) = v;
                }
            }
        }
}

// ---------------------------------------------------------------------------
// LayerNorm over E=1024; optional fp32 out and/or fp16 hi out.
// ---------------------------------------------------------------------------
__global__ __launch_bounds__(256)
void ln_kernel(const float* __restrict__ x, float* __restrict__ o,
               __half* __restrict__ oh,
               const float* __restrict__ g, const float* __restrict__ b)
{
    __shared__ float sm[18];
    const int row = blockIdx.x;
    const int t   = threadIdx.x;
    float4 v = reinterpret_cast<const float4*>(x + (size_t)row * E_DIM)[t];
    float s  = v.x + v.y + v.z + v.w;
    float ss = v.x * v.x + v.y * v.y + v.z * v.z + v.w * v.w;
#pragma unroll
    for (int off = 16; off > 0; off >>= 1) {
        s  += __shfl_xor_sync(0xffffffffu, s, off);
        ss += __shfl_xor_sync(0xffffffffu, ss, off);
    }
    const int wp = t >> 5, lane = t & 31;
    if (lane == 0) { sm[wp] = s; sm[8 + wp] = ss; }
    __syncthreads();
    if (t < 32) {
        s  = (t < 8) ? sm[t]     : 0.f;
        ss = (t < 8) ? sm[8 + t] : 0.f;
#pragma unroll
        for (int off = 4; off > 0; off >>= 1) {
            s  += __shfl_xor_sync(0xffffffffu, s, off);
            ss += __shfl_xor_sync(0xffffffffu, ss, off);
        }
        if (t == 0) {
            float mean = s * (1.f / E_DIM);
            float var  = ss * (1.f / E_DIM) - mean * mean;
            sm[16] = mean;
            sm[17] = rsqrtf(var + 1e-5f);
        }
    }
    __syncthreads();
    const float mean = sm[16], inv = sm[17];
    float4 gg = reinterpret_cast<const float4*>(g)[t];
    float4 bb = reinterpret_cast<const float4*>(b)[t];
    float4 ov;
    ov.x = (v.x - mean) * inv * gg.x + bb.x;
    ov.y = (v.y - mean) * inv * gg.y + bb.y;
    ov.z = (v.z - mean) * inv * gg.z + bb.z;
    ov.w = (v.w - mean) * inv * gg.w + bb.w;
    if (o) reinterpret_cast<float4*>(o + (size_t)row * E_DIM)[t] = ov;
    if (oh) {
        uint2 hh;
        hh.x = h2pack(ov.x, ov.y);
        hh.y = h2pack(ov.z, ov.w);
        reinterpret_cast<uint2*>(oh + (size_t)row * E_DIM)[t] = hh;
    }
}

// ---------------------------------------------------------------------------
// WKV recurrence, fused single kernel. Block = 512 threads = 32 channels x 16
// chunks; chunk states in smem; warp-uniform prefix; replay emits fp16 yh.
// kr layout: k at col e, v==r at col 1024+e, row stride 2048.
// ---------------------------------------------------------------------------
__global__ __launch_bounds__(512)
void wkv_fused(const float* __restrict__ kr,
               const float* __restrict__ decay, const float* __restrict__ first,
               __half* __restrict__ yh)
{
    __shared__ float s_a[NCHUNK][32], s_b[NCHUNK][32], s_p[NCHUNK][32];
    const int ch = threadIdx.x & 31;
    const int c  = threadIdx.x >> 5;          // chunk, warp-uniform
    const int e  = blockIdx.x * 32 + ch;
    const int b  = blockIdx.y;
    const float w = -expf(decay[e]);
    const float u = first[e];

    const size_t base  = ((size_t)b * T_LEN + (size_t)c * CHLEN) * 2048 + e;
    const size_t ybase = ((size_t)b * T_LEN + (size_t)c * CHLEN) * E_DIM + e;
    const float* kp = kr + base;

    // pass 1: chunk-local scan from zero state
    float aa = 0.f, bb = 0.f, pp = -1e38f;
#pragma unroll 4
    for (int t = 0; t < CHLEN; t++) {
        float kt = kp[(size_t)t * 2048];
        float vt = kp[(size_t)t * 2048 + 1024];
        float ww = pp + w;
        float p  = fmaxf(ww, kt);
        float e1 = expf(ww - p), e2 = expf(kt - p);
        aa = e1 * aa + e2 * vt;
        bb = e1 * bb + e2;
        pp = p;
    }
    s_a[c][ch] = aa; s_b[c][ch] = bb; s_p[c][ch] = pp;
    __syncthreads();

    // prefix over previous chunks (<=15 iters, warp-uniform trip count)
    aa = 0.f; bb = 0.f; pp = -1e38f;
    for (int j = 0; j < c; j++) {
        float pd = pp + (float)CHLEN * w;
        float a2 = s_a[j][ch], b2 = s_b[j][ch], p2 = s_p[j][ch];
        float p  = fmaxf(pd, p2);
        float e1 = expf(pd - p), e2 = expf(p2 - p);
        aa = e1 * aa + e2 * a2;
        bb = e1 * bb + e2 * b2;
        pp = p;
    }

    // replay emitting y = sigmoid(r) * wkv  (v == r)
    for (int t = 0; t < CHLEN; t++) {
        float kt = kp[(size_t)t * 2048];
        float vt = kp[(size_t)t * 2048 + 1024];
        float ww = u + kt;
        float p  = fmaxf(pp, ww);
        float e1 = expf(pp - p), e2 = expf(ww - p);
        float yt = (e1 * aa + e2 * vt) / (e1 * bb + e2);
        float ys = yt * (1.f / (1.f + expf(-vt)));
        yh[ybase + (size_t)t * E_DIM] = __float2half_rn(ys);
        float ww2 = pp + w;
        float p2  = fmaxf(ww2, kt);
        e1 = expf(ww2 - p2); e2 = expf(kt - p2);
        aa = e1 * aa + e2 * vt;
        bb = e1 * bb + e2;
        pp = p2;
    }
}

// ---------------------------------------------------------------------------
// Host orchestration
// ---------------------------------------------------------------------------
static void set_smem_attrs() {
    cudaFuncSetAttribute(gemm_f16<EPI_BIAS, 2>, cudaFuncAttributeMaxDynamicSharedMemorySize, SMEM_NP2);
    cudaFuncSetAttribute(gemm_f16<EPI_NONE, 1>, cudaFuncAttributeMaxDynamicSharedMemorySize, SMEM_NP1);
    cudaFuncSetAttribute(gemm_f16<EPI_FF,   1>, cudaFuncAttributeMaxDynamicSharedMemorySize, SMEM_NP1);
    cudaFuncSetAttribute(gemm_f16<EPI_ADD,  1>, cudaFuncAttributeMaxDynamicSharedMemorySize, SMEM_NP1);
    cudaFuncSetAttribute(gemm_f16<EPI_CMIX, 1>, cudaFuncAttributeMaxDynamicSharedMemorySize, SMEM_NP1);
}

extern "C" void kernel_launch(void* const* d_in, const int* in_sizes, int n_in,
                              void* d_out, int out_size)
{
    const float* inp    = (const float*)d_in[0];
    const float* W_in   = (const float*)d_in[1];
    const float* b_in   = (const float*)d_in[2];
    const float* ln0g   = (const float*)d_in[3];
    const float* ln0b   = (const float*)d_in[4];
    const float* l0ln1g = (const float*)d_in[5];
    const float* l0ln1b = (const float*)d_in[6];
    const float* l0ln2g = (const float*)d_in[7];
    const float* l0ln2b = (const float*)d_in[8];
    const float* l0cmk  = (const float*)d_in[9];
    const float* l0cmv  = (const float*)d_in[10];
    const float* l0cmr  = (const float*)d_in[11];
    const float* l0ffk  = (const float*)d_in[12];
    const float* l0ffv  = (const float*)d_in[13];
    const float* l0ffr  = (const float*)d_in[14];
    const float* tmk    = (const float*)d_in[15];
    const float* tmr    = (const float*)d_in[16];
    const float* tmo    = (const float*)d_in[17];
    const float* tmdec  = (const float*)d_in[18];
    const float* tmfst  = (const float*)d_in[19];
    const float* ln1g   = (const float*)d_in[20];
    const float* ln1b   = (const float*)d_in[21];
    const float* ln2g   = (const float*)d_in[22];
    const float* ln2b   = (const float*)d_in[23];
    const float* ffk    = (const float*)d_in[24];
    const float* ffv    = (const float*)d_in[25];
    const float* ffr    = (const float*)d_in[26];
    const float* outg   = (const float*)d_in[27];
    const float* outb   = (const float*)d_in[28];
    float* out = (float*)d_out;

    set_smem_attrs();

    __half *wf, *inh, *inl, *xnh, *hbh, *yh;
    float *res, *tmp, *kr, *rb;
    cudaGetSymbolAddress((void**)&wf,  g_wf);
    cudaGetSymbolAddress((void**)&inh, g_inh);
    cudaGetSymbolAddress((void**)&inl, g_inl);
    cudaGetSymbolAddress((void**)&xnh, g_xnh);
    cudaGetSymbolAddress((void**)&hbh, g_hbh);
    cudaGetSymbolAddress((void**)&yh,  g_yh);
    cudaGetSymbolAddress((void**)&res, g_res);
    cudaGetSymbolAddress((void**)&tmp, g_tmp);
    cudaGetSymbolAddress((void**)&kr,  g_kr);
    cudaGetSymbolAddress((void**)&rb,  g_r);

    // ---- weight conversion: one job-table launch ----
    ConvJobs jobs;
    size_t off = 0;
    int ji = 0;
    auto addjob = [&](const float* src, size_t n, size_t dofs) {
        jobs.src[ji] = src;
        jobs.n[ji]   = (unsigned long long)n;
        jobs.ofs[ji] = (unsigned long long)dofs;
        ji++;
    };
    auto alloc = [&](size_t n) -> size_t { size_t o = off; off += n; return o; };

    const size_t o_win = alloc((size_t)E_DIM * D_IN);
    addjob(W_in, (size_t)E_DIM * D_IN, o_win);
    const size_t o_cm = alloc(FFL_);                 // l0 cmk (4096) + cmr (1024)
    addjob(l0cmk, FE_, o_cm);
    addjob(l0cmr, EE_, o_cm + FE_);
    const size_t o_cmv = alloc(FE_);
    addjob(l0cmv, FE_, o_cmv);
    const size_t o_lff = alloc(FFL_);                // l0 ffk + ffr
    addjob(l0ffk, FE_, o_lff);
    addjob(l0ffr, EE_, o_lff + FE_);
    const size_t o_lffv = alloc(FE_);
    addjob(l0ffv, FE_, o_lffv);
    const size_t o_kr = alloc((size_t)NLAYER * KRL_);
    for (int l = 0; l < NLAYER; l++) {
        addjob(tmk + (size_t)l * EE_, EE_, o_kr + (size_t)l * KRL_);
        addjob(tmr + (size_t)l * EE_, EE_, o_kr + (size_t)l * KRL_ + EE_);
    }
    const size_t o_tmo = alloc((size_t)NLAYER * EE_);
    addjob(tmo, (size_t)NLAYER * EE_, o_tmo);
    const size_t o_ff = alloc((size_t)NLAYER * FFL_);
    for (int l = 0; l < NLAYER; l++) {
        addjob(ffk + (size_t)l * FE_, FE_, o_ff + (size_t)l * FFL_);
        addjob(ffr + (size_t)l * EE_, EE_, o_ff + (size_t)l * FFL_ + FE_);
    }
    const size_t o_ffv = alloc((size_t)NLAYER * FE_);
    addjob(ffv, (size_t)NLAYER * FE_, o_ffv);

    convert_w<<<dim3(640, NJOBS), 256>>>(jobs, wf);
    convert_pair<<<1024, 256>>>((const float4*)inp, (uint2*)inh, (uint2*)inl,
                                (int)((size_t)BTOK * D_IN / 4));

    const dim3 gE   (E_DIM / TN,  BTOK / TM);   // (8, 32)
    const dim3 gKR  (2048 / TN,   BTOK / TM);   // (16, 32)
    const dim3 gFF  (5120 / TN,   BTOK / TM);   // (40, 32)
    const dim3 gWKV (E_DIM / 32,  BATCH);       // (32, 4) = 128 CTAs x 512 thr

    // x = inputs @ W_in^T + b_in ; res = LN(x, ln0)
    gemm_f16<EPI_BIAS, 2><<<gE, GT, SMEM_NP2>>>(inh, inl, wf + o_win,
        tmp, BTOK, E_DIM, D_IN, b_in, nullptr, nullptr, nullptr, 0);
    ln_kernel<<<BTOK, 256>>>(tmp, res, nullptr, ln0g, ln0b);

    // channel mix (fused ffk+ffr GEMM 1-prod, ffv GEMM 1-prod)
    auto cmix = [&](const float* lg, const float* lb, size_t okr_, size_t ov_) {
        ln_kernel<<<BTOK, 256>>>(res, nullptr, xnh, lg, lb);
        gemm_f16<EPI_FF, 1><<<gFF, GT, SMEM_NP1>>>(xnh, nullptr, wf + okr_,
            rb, BTOK, 5120, E_DIM, nullptr, nullptr, nullptr, hbh, FOUR_E);
        gemm_f16<EPI_CMIX, 1><<<gE, GT, SMEM_NP1>>>(hbh, nullptr, wf + ov_,
            res, BTOK, E_DIM, FOUR_E, nullptr, res, rb, nullptr, 0);
    };

    cmix(l0ln1g, l0ln1b, o_cm,  o_cmv);
    cmix(l0ln2g, l0ln2b, o_lff, o_lffv);

    for (int l = 0; l < NLAYER; l++) {
        const size_t oE = (size_t)l * E_DIM;

        ln_kernel<<<BTOK, 256>>>(res, nullptr, xnh, ln1g + oE, ln1b + oE);
        gemm_f16<EPI_NONE, 1><<<gKR, GT, SMEM_NP1>>>(xnh, nullptr, wf + o_kr + (size_t)l * KRL_,
            kr, BTOK, 2048, E_DIM, nullptr, nullptr, nullptr, nullptr, 0);
        wkv_fused<<<gWKV, 512>>>(kr, tmdec + oE, tmfst + oE, yh);
        gemm_f16<EPI_ADD, 1><<<gE, GT, SMEM_NP1>>>(yh, nullptr, wf + o_tmo + (size_t)l * EE_,
            res, BTOK, E_DIM, E_DIM, nullptr, res, nullptr, nullptr, 0);

        ln_kernel<<<BTOK, 256>>>(res, nullptr, xnh, ln2g + oE, ln2b + oE);
        gemm_f16<EPI_FF, 1><<<gFF, GT, SMEM_NP1>>>(xnh, nullptr, wf + o_ff + (size_t)l * FFL_,
            rb, BTOK, 5120, E_DIM, nullptr, nullptr, nullptr, hbh, FOUR_E);
        gemm_f16<EPI_CMIX, 1><<<gE, GT, SMEM_NP1>>>(hbh, nullptr, wf + o_ffv + (size_t)l * FE_,
            res, BTOK, E_DIM, FOUR_E, nullptr, res, rb, nullptr, 0);
    }

    ln_kernel<<<BTOK, 256>>>(res, out, nullptr, outg, outb);
}

// round 12
// speedup vs baseline: 1.7703x; 1.0218x over previous
#include <cuda_runtime.h>
#include <cuda_fp16.h>
#include <cstdint>
#include <math.h>

// ---------------------------------------------------------------------------
// RWKV forward. GEMMs: mma.sync fp16, single-product everywhere except the
// tiny W_in GEMM (2-product). k+r and ffk+ffr fused wide GEMMs. WKV = single
// fused kernel (chunked scan, smem states, __expf). LN = warp-per-row.
// ---------------------------------------------------------------------------

#define E_DIM   1024
#define FOUR_E  4096
#define D_IN    512
#define BTOK    4096
#define T_LEN   1024
#define BATCH   4
#define NLAYER  11
#define NCHUNK  16
#define CHLEN   64

#define EE_  1048576ull          // E*E
#define FE_  4194304ull          // 4E*E
#define KRL_ (2ull * EE_)        // fused k+r block per layer
#define FFL_ (FE_ + EE_)         // fused ffk+ffr block per layer

// ---------------- device-global scratch (no allocation allowed) ------------
#define WBUF_ELEMS 157810688ull
__device__ __half g_wf[WBUF_ELEMS];

__device__ __half g_inh[BTOK * D_IN],   g_inl[BTOK * D_IN];
__device__ __half g_xnh[BTOK * E_DIM];
__device__ __half g_hbh[BTOK * FOUR_E];
__device__ __half g_yh [BTOK * E_DIM];

__device__ float g_res[BTOK * E_DIM];
__device__ float g_tmp[BTOK * E_DIM];
__device__ float g_kr [BTOK * 2 * E_DIM];
__device__ float g_r  [BTOK * E_DIM];

// ---------------------------------------------------------------------------
// helpers
// ---------------------------------------------------------------------------
__device__ __forceinline__ uint32_t smem_u32(const void* p) {
    uint32_t a;
    asm("{ .reg .u64 t; cvta.to.shared.u64 t, %1; cvt.u32.u64 %0, t; }" : "=r"(a) : "l"(p));
    return a;
}
__device__ __forceinline__ void ldm_x4(uint32_t* r, uint32_t addr) {
    asm volatile("ldmatrix.sync.aligned.m8n8.x4.shared.b16 {%0,%1,%2,%3}, [%4];"
        : "=r"(r[0]), "=r"(r[1]), "=r"(r[2]), "=r"(r[3]) : "r"(addr));
}
__device__ __forceinline__ void mma_f16(float* d, const uint32_t* a, uint32_t b0, uint32_t b1) {
    asm volatile("mma.sync.aligned.m16n8k16.row.col.f32.f16.f16.f32 "
        "{%0,%1,%2,%3}, {%4,%5,%6,%7}, {%8,%9}, {%0,%1,%2,%3};"
        : "+f"(d[0]), "+f"(d[1]), "+f"(d[2]), "+f"(d[3])
        : "r"(a[0]), "r"(a[1]), "r"(a[2]), "r"(a[3]), "r"(b0), "r"(b1));
}
__device__ __forceinline__ void cp16(uint32_t s, const void* g) {
    asm volatile("cp.async.cg.shared.global [%0], [%1], 16;" :: "r"(s), "l"(g));
}
__device__ __forceinline__ void cp_commit() {
    asm volatile("cp.async.commit_group;" ::: "memory");
}
template <int N> __device__ __forceinline__ void cp_wait() {
    asm volatile("cp.async.wait_group %0;" :: "n"(N) : "memory");
}
__device__ __forceinline__ void splith2(float2 v, uint32_t& h, uint32_t& l) {
    __half2 hh = __floats2half2_rn(v.x, v.y);
    h = *reinterpret_cast<uint32_t*>(&hh);
    float2 b = __half22float2(hh);
    __half2 ll = __floats2half2_rn(v.x - b.x, v.y - b.y);
    l = *reinterpret_cast<uint32_t*>(&ll);
}
__device__ __forceinline__ uint32_t h2pack(float a, float b) {
    __half2 h = __floats2half2_rn(a, b);
    return *reinterpret_cast<uint32_t*>(&h);
}

// ---------------------------------------------------------------------------
// weight conversion: fp32 -> fp16, all tensors in ONE launch (job table)
// ---------------------------------------------------------------------------
#define NJOBS 53
struct ConvJobs {
    const float* src[NJOBS];
    unsigned long long n[NJOBS];
    unsigned long long ofs[NJOBS];
};

__global__ void convert_w(ConvJobs jobs, __half* __restrict__ dst)
{
    const int jid = blockIdx.y;
    const float4* src = reinterpret_cast<const float4*>(jobs.src[jid]);
    uint4* d = reinterpret_cast<uint4*>(dst + jobs.ofs[jid]);
    const long long n8 = (long long)(jobs.n[jid] >> 3);
    const long long stride = (long long)gridDim.x * blockDim.x;
    for (long long i = blockIdx.x * (long long)blockDim.x + threadIdx.x; i < n8; i += stride) {
        float4 a = src[2 * i];
        float4 b = src[2 * i + 1];
        uint4 o;
        o.x = h2pack(a.x, a.y); o.y = h2pack(a.z, a.w);
        o.z = h2pack(b.x, b.y); o.w = h2pack(b.z, b.w);
        d[i] = o;
    }
}

__global__ void convert_pair(const float4* __restrict__ src,
                             uint2* __restrict__ h, uint2* __restrict__ l, int n4)
{
    const int stride = gridDim.x * blockDim.x;
    for (int i = blockIdx.x * blockDim.x + threadIdx.x; i < n4; i += stride) {
        float4 v = src[i];
        uint2 hh, ll;
        splith2(make_float2(v.x, v.y), hh.x, ll.x);
        splith2(make_float2(v.z, v.w), hh.y, ll.y);
        h[i] = hh;
        l[i] = ll;
    }
}

// ---------------------------------------------------------------------------
// GEMM: C[M,N] = A[M,K] @ W[N,K]^T. A = fp16 (h, optional l), B = fp16.
// CTA 128x128x32, 256 threads (8 warps: 4m x 2n), warp tile 32x64, 3 stages,
// 2 CTAs per SM. NPROD = 1 or 2 split products.
// ---------------------------------------------------------------------------
#define TM 128
#define TN 128
#define TK 32
#define GT 256
#define STAGES 3
#define ROWB 80
#define PARTB (128 * ROWB)       // 10240

#define EPI_NONE   0
#define EPI_BIAS   1
#define EPI_FF     2
#define EPI_ADD    3
#define EPI_CMIX   4

#define SMEM_NP2 (STAGES * 3 * PARTB)   // 92160
#define SMEM_NP1 (STAGES * 2 * PARTB)   // 61440

template <int EPI, int NPROD>
__global__ __launch_bounds__(GT, 2)
void gemm_f16(const __half* __restrict__ Ah, const __half* __restrict__ Al,
              const __half* __restrict__ Bh,
              float* __restrict__ C, int M, int N, int K,
              const float* __restrict__ bias,
              const float* __restrict__ Cin,
              const float* __restrict__ Rg,
              __half* __restrict__ Oh, int NSplit)
{
    constexpr int STAGE_SZ = (NPROD + 1) * PARTB;
    constexpr int OFF_AL = PARTB;                 // valid when NPROD==2
    constexpr int OFF_B  = NPROD * PARTB;

    extern __shared__ char smem[];
    const uint32_t sbase = smem_u32(smem);
    const int tid  = threadIdx.x;
    const int lane = tid & 31;
    const int wid  = tid >> 5;
    const int wm   = wid & 3;
    const int wn   = wid >> 2;
    const int bm   = blockIdx.y * TM;
    const int bn   = blockIdx.x * TN;

    const int lrow  = lane & 15;
    const int lchun = lane >> 4;

    float acc[2][8][4];
#pragma unroll
    for (int i = 0; i < 2; i++)
#pragma unroll
        for (int j = 0; j < 8; j++)
#pragma unroll
            for (int q = 0; q < 4; q++) acc[i][j][q] = 0.f;

    const int S = K / TK;

    auto issue = [&](int s, int buf) {
        const uint32_t sb = sbase + buf * STAGE_SZ;
        const int k0 = s * TK;
#pragma unroll
        for (int i = 0; i < 2; i++) {
            int idx = tid + i * GT;
            int row = idx >> 2, seg = idx & 3;
            uint32_t sa = sb + row * ROWB + seg * 16;
            size_t go = (size_t)(bm + row) * K + k0 + seg * 8;
            cp16(sa, Ah + go);
            if (NPROD == 2) cp16(sa + OFF_AL, Al + go);
        }
#pragma unroll
        for (int i = 0; i < 2; i++) {
            int idx = tid + i * GT;
            int row = idx >> 2, seg = idx & 3;
            uint32_t sa = sb + OFF_B + row * ROWB + seg * 16;
            size_t go = (size_t)(bn + row) * K + k0 + seg * 8;
            cp16(sa, Bh + go);
        }
        cp_commit();
    };

    issue(0, 0);
    issue(1, 1);

    for (int s = 0; s < S; s++) {
        const int buf = s % STAGES;
        cp_wait<1>();
        __syncthreads();

        const uint32_t sb = sbase + buf * STAGE_SZ;
#pragma unroll
        for (int kk = 0; kk < 2; kk++) {
            const uint32_t koff = (uint32_t)((kk * 2 + lchun) * 16);
            uint32_t ah[2][4], al[2][4];
#pragma unroll
            for (int mt = 0; mt < 2; mt++) {
                uint32_t aa = sb + (uint32_t)((wm * 32 + mt * 16 + lrow) * ROWB) + koff;
                ldm_x4(ah[mt], aa);
                if (NPROD == 2) ldm_x4(al[mt], aa + OFF_AL);
            }
#pragma unroll
            for (int bg = 0; bg < 2; bg++) {
                uint32_t bh[2][4];
#pragma unroll
                for (int bt = 0; bt < 2; bt++) {
                    uint32_t ba = sb + OFF_B +
                        (uint32_t)((wn * 64 + (bg * 2 + bt) * 16 + lrow) * ROWB) + koff;
                    ldm_x4(bh[bt], ba);
                }
#pragma unroll
                for (int mt = 0; mt < 2; mt++)
#pragma unroll
                    for (int bt = 0; bt < 2; bt++)
#pragma unroll
                        for (int j = 0; j < 2; j++)
                            mma_f16(acc[mt][bg * 4 + bt * 2 + j], ah[mt], bh[bt][j], bh[bt][2 + j]);
                if (NPROD == 2) {
#pragma unroll
                    for (int mt = 0; mt < 2; mt++)
#pragma unroll
                        for (int bt = 0; bt < 2; bt++)
#pragma unroll
                            for (int j = 0; j < 2; j++)
                                mma_f16(acc[mt][bg * 4 + bt * 2 + j], al[mt], bh[bt][j], bh[bt][2 + j]);
                }
            }
        }
        if (s + 2 < S) issue(s + 2, (s + 2) % STAGES);
    }

    // epilogue
#pragma unroll
    for (int mt = 0; mt < 2; mt++)
#pragma unroll
        for (int nt = 0; nt < 8; nt++) {
            const int row0 = bm + wm * 32 + mt * 16 + (lane >> 2);
            const int col  = bn + wn * 64 + (nt >> 1) * 16 + (nt & 1) * 8 + (lane & 3) * 2;
#pragma unroll
            for (int h = 0; h < 2; h++) {
                const int r = row0 + h * 8;
                float2 v = make_float2(acc[mt][nt][2 * h + 0], acc[mt][nt][2 * h + 1]);
                if (EPI == EPI_BIAS) {
                    float2 bb = *reinterpret_cast<const float2*>(bias + col);
                    v.x += bb.x; v.y += bb.y;
                    *reinterpret_cast<float2*>(C + (size_t)r * N + col) = v;
                }
                if (EPI == EPI_NONE) {
                    *reinterpret_cast<float2*>(C + (size_t)r * N + col) = v;
                }
                if (EPI == EPI_FF) {
                    if (col < NSplit) {
                        v.x = v.x > 0.f ? v.x * v.x : 0.f;
                        v.y = v.y > 0.f ? v.y * v.y : 0.f;
                        *reinterpret_cast<uint32_t*>(Oh + (size_t)r * NSplit + col) =
                            h2pack(v.x, v.y);
                    } else {
                        *reinterpret_cast<float2*>(C + (size_t)r * (N - NSplit) + col - NSplit) = v;
                    }
                }
                if (EPI == EPI_ADD) {
                    const size_t idx = (size_t)r * N + col;
                    float2 ci = *reinterpret_cast<const float2*>(Cin + idx);
                    v.x += ci.x; v.y += ci.y;
                    *reinterpret_cast<float2*>(C + idx) = v;
                }
                if (EPI == EPI_CMIX) {
                    const size_t idx = (size_t)r * N + col;
                    float2 ci = *reinterpret_cast<const float2*>(Cin + idx);
                    float2 rr = *reinterpret_cast<const float2*>(Rg + idx);
                    v.x = ci.x + v.x * (1.f / (1.f + __expf(-rr.x)));
                    v.y = ci.y + v.y * (1.f / (1.f + __expf(-rr.y)));
                    *reinterpret_cast<float2*>(C + idx) = v;
                }
            }
        }
}

// ---------------------------------------------------------------------------
// LayerNorm over E=1024, warp-per-row: 256 threads = 8 warps = 8 rows/CTA,
// shuffle-only reduction, 8 float4 per lane kept in registers.
// ---------------------------------------------------------------------------
__global__ __launch_bounds__(256)
void ln_kernel(const float* __restrict__ x, float* __restrict__ o,
               __half* __restrict__ oh,
               const float* __restrict__ g, const float* __restrict__ b)
{
    const int lane = threadIdx.x & 31;
    const int row  = blockIdx.x * 8 + (threadIdx.x >> 5);

    const float4* xr = reinterpret_cast<const float4*>(x + (size_t)row * E_DIM);
    float4 v[8];
    float s = 0.f, ss = 0.f;
#pragma unroll
    for (int i = 0; i < 8; i++) {
        v[i] = xr[lane + i * 32];
        s  += v[i].x + v[i].y + v[i].z + v[i].w;
        ss += v[i].x * v[i].x + v[i].y * v[i].y + v[i].z * v[i].z + v[i].w * v[i].w;
    }
#pragma unroll
    for (int off = 16; off > 0; off >>= 1) {
        s  += __shfl_xor_sync(0xffffffffu, s, off);
        ss += __shfl_xor_sync(0xffffffffu, ss, off);
    }
    const float mean = s * (1.f / E_DIM);
    const float inv  = rsqrtf(ss * (1.f / E_DIM) - mean * mean + 1e-5f);

#pragma unroll
    for (int i = 0; i < 8; i++) {
        const int c = lane + i * 32;
        float4 gg = reinterpret_cast<const float4*>(g)[c];
        float4 bb = reinterpret_cast<const float4*>(b)[c];
        float4 ov;
        ov.x = (v[i].x - mean) * inv * gg.x + bb.x;
        ov.y = (v[i].y - mean) * inv * gg.y + bb.y;
        ov.z = (v[i].z - mean) * inv * gg.z + bb.z;
        ov.w = (v[i].w - mean) * inv * gg.w + bb.w;
        if (o) reinterpret_cast<float4*>(o + (size_t)row * E_DIM)[c] = ov;
        if (oh) {
            uint2 hh;
            hh.x = h2pack(ov.x, ov.y);
            hh.y = h2pack(ov.z, ov.w);
            reinterpret_cast<uint2*>(oh + (size_t)row * E_DIM)[c] = hh;
        }
    }
}

// ---------------------------------------------------------------------------
// WKV recurrence, fused single kernel. Block = 512 threads = 32 channels x 16
// chunks; chunk states in smem; warp-uniform prefix; replay emits fp16 yh.
// kr layout: k at col e, v==r at col 1024+e, row stride 2048. Fast __expf.
// ---------------------------------------------------------------------------
__global__ __launch_bounds__(512)
void wkv_fused(const float* __restrict__ kr,
               const float* __restrict__ decay, const float* __restrict__ first,
               __half* __restrict__ yh)
{
    __shared__ float s_a[NCHUNK][32], s_b[NCHUNK][32], s_p[NCHUNK][32];
    const int ch = threadIdx.x & 31;
    const int c  = threadIdx.x >> 5;          // chunk, warp-uniform
    const int e  = blockIdx.x * 32 + ch;
    const int b  = blockIdx.y;
    const float w = -__expf(decay[e]);
    const float u = first[e];

    const size_t base  = ((size_t)b * T_LEN + (size_t)c * CHLEN) * 2048 + e;
    const size_t ybase = ((size_t)b * T_LEN + (size_t)c * CHLEN) * E_DIM + e;
    const float* kp = kr + base;

    // pass 1: chunk-local scan from zero state
    float aa = 0.f, bb = 0.f, pp = -1e38f;
#pragma unroll 4
    for (int t = 0; t < CHLEN; t++) {
        float kt = kp[(size_t)t * 2048];
        float vt = kp[(size_t)t * 2048 + 1024];
        float ww = pp + w;
        float p  = fmaxf(ww, kt);
        float e1 = __expf(ww - p), e2 = __expf(kt - p);
        aa = e1 * aa + e2 * vt;
        bb = e1 * bb + e2;
        pp = p;
    }
    s_a[c][ch] = aa; s_b[c][ch] = bb; s_p[c][ch] = pp;
    __syncthreads();

    // prefix over previous chunks (<=15 iters, warp-uniform trip count)
    aa = 0.f; bb = 0.f; pp = -1e38f;
    for (int j = 0; j < c; j++) {
        float pd = pp + (float)CHLEN * w;
        float a2 = s_a[j][ch], b2 = s_b[j][ch], p2 = s_p[j][ch];
        float p  = fmaxf(pd, p2);
        float e1 = __expf(pd - p), e2 = __expf(p2 - p);
        aa = e1 * aa + e2 * a2;
        bb = e1 * bb + e2 * b2;
        pp = p;
    }

    // replay emitting y = sigmoid(r) * wkv  (v == r)
    for (int t = 0; t < CHLEN; t++) {
        float kt = kp[(size_t)t * 2048];
        float vt = kp[(size_t)t * 2048 + 1024];
        float ww = u + kt;
        float p  = fmaxf(pp, ww);
        float e1 = __expf(pp - p), e2 = __expf(ww - p);
        float yt = (e1 * aa + e2 * vt) / (e1 * bb + e2);
        float ys = yt * (1.f / (1.f + __expf(-vt)));
        yh[ybase + (size_t)t * E_DIM] = __float2half_rn(ys);
        float ww2 = pp + w;
        float p2  = fmaxf(ww2, kt);
        e1 = __expf(ww2 - p2); e2 = __expf(kt - p2);
        aa = e1 * aa + e2 * vt;
        bb = e1 * bb + e2;
        pp = p2;
    }
}

// ---------------------------------------------------------------------------
// Host orchestration
// ---------------------------------------------------------------------------
static void set_smem_attrs() {
    cudaFuncSetAttribute(gemm_f16<EPI_BIAS, 2>, cudaFuncAttributeMaxDynamicSharedMemorySize, SMEM_NP2);
    cudaFuncSetAttribute(gemm_f16<EPI_NONE, 1>, cudaFuncAttributeMaxDynamicSharedMemorySize, SMEM_NP1);
    cudaFuncSetAttribute(gemm_f16<EPI_FF,   1>, cudaFuncAttributeMaxDynamicSharedMemorySize, SMEM_NP1);
    cudaFuncSetAttribute(gemm_f16<EPI_ADD,  1>, cudaFuncAttributeMaxDynamicSharedMemorySize, SMEM_NP1);
    cudaFuncSetAttribute(gemm_f16<EPI_CMIX, 1>, cudaFuncAttributeMaxDynamicSharedMemorySize, SMEM_NP1);
}

extern "C" void kernel_launch(void* const* d_in, const int* in_sizes, int n_in,
                              void* d_out, int out_size)
{
    const float* inp    = (const float*)d_in[0];
    const float* W_in   = (const float*)d_in[1];
    const float* b_in   = (const float*)d_in[2];
    const float* ln0g   = (const float*)d_in[3];
    const float* ln0b   = (const float*)d_in[4];
    const float* l0ln1g = (const float*)d_in[5];
    const float* l0ln1b = (const float*)d_in[6];
    const float* l0ln2g = (const float*)d_in[7];
    const float* l0ln2b = (const float*)d_in[8];
    const float* l0cmk  = (const float*)d_in[9];
    const float* l0cmv  = (const float*)d_in[10];
    const float* l0cmr  = (const float*)d_in[11];
    const float* l0ffk  = (const float*)d_in[12];
    const float* l0ffv  = (const float*)d_in[13];
    const float* l0ffr  = (const float*)d_in[14];
    const float* tmk    = (const float*)d_in[15];
    const float* tmr    = (const float*)d_in[16];
    const float* tmo    = (const float*)d_in[17];
    const float* tmdec  = (const float*)d_in[18];
    const float* tmfst  = (const float*)d_in[19];
    const float* ln1g   = (const float*)d_in[20];
    const float* ln1b   = (const float*)d_in[21];
    const float* ln2g   = (const float*)d_in[22];
    const float* ln2b   = (const float*)d_in[23];
    const float* ffk    = (const float*)d_in[24];
    const float* ffv    = (const float*)d_in[25];
    const float* ffr    = (const float*)d_in[26];
    const float* outg   = (const float*)d_in[27];
    const float* outb   = (const float*)d_in[28];
    float* out = (float*)d_out;

    set_smem_attrs();

    __half *wf, *inh, *inl, *xnh, *hbh, *yh;
    float *res, *tmp, *kr, *rb;
    cudaGetSymbolAddress((void**)&wf,  g_wf);
    cudaGetSymbolAddress((void**)&inh, g_inh);
    cudaGetSymbolAddress((void**)&inl, g_inl);
    cudaGetSymbolAddress((void**)&xnh, g_xnh);
    cudaGetSymbolAddress((void**)&hbh, g_hbh);
    cudaGetSymbolAddress((void**)&yh,  g_yh);
    cudaGetSymbolAddress((void**)&res, g_res);
    cudaGetSymbolAddress((void**)&tmp, g_tmp);
    cudaGetSymbolAddress((void**)&kr,  g_kr);
    cudaGetSymbolAddress((void**)&rb,  g_r);

    // ---- weight conversion: one job-table launch ----
    ConvJobs jobs;
    size_t off = 0;
    int ji = 0;
    auto addjob = [&](const float* src, size_t n, size_t dofs) {
        jobs.src[ji] = src;
        jobs.n[ji]   = (unsigned long long)n;
        jobs.ofs[ji] = (unsigned long long)dofs;
        ji++;
    };
    auto alloc = [&](size_t n) -> size_t { size_t o = off; off += n; return o; };

    const size_t o_win = alloc((size_t)E_DIM * D_IN);
    addjob(W_in, (size_t)E_DIM * D_IN, o_win);
    const size_t o_cm = alloc(FFL_);                 // l0 cmk (4096) + cmr (1024)
    addjob(l0cmk, FE_, o_cm);
    addjob(l0cmr, EE_, o_cm + FE_);
    const size_t o_cmv = alloc(FE_);
    addjob(l0cmv, FE_, o_cmv);
    const size_t o_lff = alloc(FFL_);                // l0 ffk + ffr
    addjob(l0ffk, FE_, o_lff);
    addjob(l0ffr, EE_, o_lff + FE_);
    const size_t o_lffv = alloc(FE_);
    addjob(l0ffv, FE_, o_lffv);
    const size_t o_kr = alloc((size_t)NLAYER * KRL_);
    for (int l = 0; l < NLAYER; l++) {
        addjob(tmk + (size_t)l * EE_, EE_, o_kr + (size_t)l * KRL_);
        addjob(tmr + (size_t)l * EE_, EE_, o_kr + (size_t)l * KRL_ + EE_);
    }
    const size_t o_tmo = alloc((size_t)NLAYER * EE_);
    addjob(tmo, (size_t)NLAYER * EE_, o_tmo);
    const size_t o_ff = alloc((size_t)NLAYER * FFL_);
    for (int l = 0; l < NLAYER; l++) {
        addjob(ffk + (size_t)l * FE_, FE_, o_ff + (size_t)l * FFL_);
        addjob(ffr + (size_t)l * EE_, EE_, o_ff + (size_t)l * FFL_ + FE_);
    }
    const size_t o_ffv = alloc((size_t)NLAYER * FE_);
    addjob(ffv, (size_t)NLAYER * FE_, o_ffv);

    convert_w<<<dim3(640, NJOBS), 256>>>(jobs, wf);
    convert_pair<<<1024, 256>>>((const float4*)inp, (uint2*)inh, (uint2*)inl,
                                (int)((size_t)BTOK * D_IN / 4));

    const dim3 gE   (E_DIM / TN,  BTOK / TM);   // (8, 32)
    const dim3 gKR  (2048 / TN,   BTOK / TM);   // (16, 32)
    const dim3 gFF  (5120 / TN,   BTOK / TM);   // (40, 32)
    const dim3 gWKV (E_DIM / 32,  BATCH);       // (32, 4) = 128 CTAs x 512 thr
    const int  gLN  = BTOK / 8;                 // 512 CTAs, warp-per-row

    // x = inputs @ W_in^T + b_in ; res = LN(x, ln0)
    gemm_f16<EPI_BIAS, 2><<<gE, GT, SMEM_NP2>>>(inh, inl, wf + o_win,
        tmp, BTOK, E_DIM, D_IN, b_in, nullptr, nullptr, nullptr, 0);
    ln_kernel<<<gLN, 256>>>(tmp, res, nullptr, ln0g, ln0b);

    // channel mix (fused ffk+ffr GEMM 1-prod, ffv GEMM 1-prod)
    auto cmix = [&](const float* lg, const float* lb, size_t okr_, size_t ov_) {
        ln_kernel<<<gLN, 256>>>(res, nullptr, xnh, lg, lb);
        gemm_f16<EPI_FF, 1><<<gFF, GT, SMEM_NP1>>>(xnh, nullptr, wf + okr_,
            rb, BTOK, 5120, E_DIM, nullptr, nullptr, nullptr, hbh, FOUR_E);
        gemm_f16<EPI_CMIX, 1><<<gE, GT, SMEM_NP1>>>(hbh, nullptr, wf + ov_,
            res, BTOK, E_DIM, FOUR_E, nullptr, res, rb, nullptr, 0);
    };

    cmix(l0ln1g, l0ln1b, o_cm,  o_cmv);
    cmix(l0ln2g, l0ln2b, o_lff, o_lffv);

    for (int l = 0; l < NLAYER; l++) {
        const size_t oE = (size_t)l * E_DIM;

        ln_kernel<<<gLN, 256>>>(res, nullptr, xnh, ln1g + oE, ln1b + oE);
        gemm_f16<EPI_NONE, 1><<<gKR, GT, SMEM_NP1>>>(xnh, nullptr, wf + o_kr + (size_t)l * KRL_,
            kr, BTOK, 2048, E_DIM, nullptr, nullptr, nullptr, nullptr, 0);
        wkv_fused<<<gWKV, 512>>>(kr, tmdec + oE, tmfst + oE, yh);
        gemm_f16<EPI_ADD, 1><<<gE, GT, SMEM_NP1>>>(yh, nullptr, wf + o_tmo + (size_t)l * EE_,
            res, BTOK, E_DIM, E_DIM, nullptr, res, nullptr, nullptr, 0);

        ln_kernel<<<gLN, 256>>>(res, nullptr, xnh, ln2g + oE, ln2b + oE);
        gemm_f16<EPI_FF, 1><<<gFF, GT, SMEM_NP1>>>(xnh, nullptr, wf + o_ff + (size_t)l * FFL_,
            rb, BTOK, 5120, E_DIM, nullptr, nullptr, nullptr, hbh, FOUR_E);
        gemm_f16<EPI_CMIX, 1><<<gE, GT, SMEM_NP1>>>(hbh, nullptr, wf + o_ffv + (size_t)l * FE_,
            res, BTOK, E_DIM, FOUR_E, nullptr, res, rb, nullptr, 0);
    }

    ln_kernel<<<gLN, 256>>>(res, out, nullptr, outg, outb);
}

// round 13
// speedup vs baseline: 1.8032x; 1.0186x over previous
#include <cuda_runtime.h>
#include <cuda_fp16.h>
#include <cstdint>
#include <math.h>

// ---------------------------------------------------------------------------
// RWKV forward. GEMMs: mma.sync fp16, single-product (W_in 2-product).
// kr GEMM emits fp16; r-gate fp16; WKV fused, 32 chunks x 32 steps, fp16 IO.
// ---------------------------------------------------------------------------

#define E_DIM   1024
#define FOUR_E  4096
#define D_IN    512
#define BTOK    4096
#define T_LEN   1024
#define BATCH   4
#define NLAYER  11
#define NCH2    32
#define CLEN2   32

#define EE_  1048576ull          // E*E
#define FE_  4194304ull          // 4E*E
#define KRL_ (2ull * EE_)        // fused k+r block per layer
#define FFL_ (FE_ + EE_)         // fused ffk+ffr block per layer

// ---------------- device-global scratch (no allocation allowed) ------------
#define WBUF_ELEMS 157810688ull
__device__ __half g_wf[WBUF_ELEMS];

__device__ __half g_inh[BTOK * D_IN],   g_inl[BTOK * D_IN];
__device__ __half g_xnh[BTOK * E_DIM];
__device__ __half g_hbh[BTOK * FOUR_E];
__device__ __half g_yh [BTOK * E_DIM];
__device__ __half g_krh[BTOK * 2 * E_DIM];
__device__ __half g_rh [BTOK * E_DIM];

__device__ float g_res[BTOK * E_DIM];
__device__ float g_tmp[BTOK * E_DIM];

// ---------------------------------------------------------------------------
// helpers
// ---------------------------------------------------------------------------
__device__ __forceinline__ uint32_t smem_u32(const void* p) {
    uint32_t a;
    asm("{ .reg .u64 t; cvta.to.shared.u64 t, %1; cvt.u32.u64 %0, t; }" : "=r"(a) : "l"(p));
    return a;
}
__device__ __forceinline__ void ldm_x4(uint32_t* r, uint32_t addr) {
    asm volatile("ldmatrix.sync.aligned.m8n8.x4.shared.b16 {%0,%1,%2,%3}, [%4];"
        : "=r"(r[0]), "=r"(r[1]), "=r"(r[2]), "=r"(r[3]) : "r"(addr));
}
__device__ __forceinline__ void mma_f16(float* d, const uint32_t* a, uint32_t b0, uint32_t b1) {
    asm volatile("mma.sync.aligned.m16n8k16.row.col.f32.f16.f16.f32 "
        "{%0,%1,%2,%3}, {%4,%5,%6,%7}, {%8,%9}, {%0,%1,%2,%3};"
        : "+f"(d[0]), "+f"(d[1]), "+f"(d[2]), "+f"(d[3])
        : "r"(a[0]), "r"(a[1]), "r"(a[2]), "r"(a[3]), "r"(b0), "r"(b1));
}
__device__ __forceinline__ void cp16(uint32_t s, const void* g) {
    asm volatile("cp.async.cg.shared.global [%0], [%1], 16;" :: "r"(s), "l"(g));
}
__device__ __forceinline__ void cp_commit() {
    asm volatile("cp.async.commit_group;" ::: "memory");
}
template <int N> __device__ __forceinline__ void cp_wait() {
    asm volatile("cp.async.wait_group %0;" :: "n"(N) : "memory");
}
__device__ __forceinline__ void splith2(float2 v, uint32_t& h, uint32_t& l) {
    __half2 hh = __floats2half2_rn(v.x, v.y);
    h = *reinterpret_cast<uint32_t*>(&hh);
    float2 b = __half22float2(hh);
    __half2 ll = __floats2half2_rn(v.x - b.x, v.y - b.y);
    l = *reinterpret_cast<uint32_t*>(&ll);
}
__device__ __forceinline__ uint32_t h2pack(float a, float b) {
    __half2 h = __floats2half2_rn(a, b);
    return *reinterpret_cast<uint32_t*>(&h);
}

// ---------------------------------------------------------------------------
// weight conversion: fp32 -> fp16, all tensors in ONE launch (job table)
// ---------------------------------------------------------------------------
#define NJOBS 53
struct ConvJobs {
    const float* src[NJOBS];
    unsigned long long n[NJOBS];
    unsigned long long ofs[NJOBS];
};

__global__ void convert_w(ConvJobs jobs, __half* __restrict__ dst)
{
    const int jid = blockIdx.y;
    const float4* src = reinterpret_cast<const float4*>(jobs.src[jid]);
    uint4* d = reinterpret_cast<uint4*>(dst + jobs.ofs[jid]);
    const long long n8 = (long long)(jobs.n[jid] >> 3);
    const long long stride = (long long)gridDim.x * blockDim.x;
    for (long long i = blockIdx.x * (long long)blockDim.x + threadIdx.x; i < n8; i += stride) {
        float4 a = src[2 * i];
        float4 b = src[2 * i + 1];
        uint4 o;
        o.x = h2pack(a.x, a.y); o.y = h2pack(a.z, a.w);
        o.z = h2pack(b.x, b.y); o.w = h2pack(b.z, b.w);
        d[i] = o;
    }
}

__global__ void convert_pair(const float4* __restrict__ src,
                             uint2* __restrict__ h, uint2* __restrict__ l, int n4)
{
    const int stride = gridDim.x * blockDim.x;
    for (int i = blockIdx.x * blockDim.x + threadIdx.x; i < n4; i += stride) {
        float4 v = src[i];
        uint2 hh, ll;
        splith2(make_float2(v.x, v.y), hh.x, ll.x);
        splith2(make_float2(v.z, v.w), hh.y, ll.y);
        h[i] = hh;
        l[i] = ll;
    }
}

// ---------------------------------------------------------------------------
// GEMM: C[M,N] = A[M,K] @ W[N,K]^T. A = fp16 (h, optional l), B = fp16.
// CTA 128x128x32, 256 threads (8 warps: 4m x 2n), warp tile 32x64, 3 stages,
// 2 CTAs per SM. NPROD = 1 or 2 split products.
// ---------------------------------------------------------------------------
#define TM 128
#define TN 128
#define TK 32
#define GT 256
#define STAGES 3
#define ROWB 80
#define PARTB (128 * ROWB)       // 10240

#define EPI_KR     0             // write fp16, stride N
#define EPI_BIAS   1
#define EPI_FF     2
#define EPI_ADD    3
#define EPI_CMIX   4

#define SMEM_NP2 (STAGES * 3 * PARTB)   // 92160
#define SMEM_NP1 (STAGES * 2 * PARTB)   // 61440

template <int EPI, int NPROD>
__global__ __launch_bounds__(GT, 2)
void gemm_f16(const __half* __restrict__ Ah, const __half* __restrict__ Al,
              const __half* __restrict__ Bh,
              float* __restrict__ C, int M, int N, int K,
              const float* __restrict__ bias,
              const float* __restrict__ Cin,
              const __half* __restrict__ Rg,
              __half* __restrict__ Oh, __half* __restrict__ Or, int NSplit)
{
    constexpr int STAGE_SZ = (NPROD + 1) * PARTB;
    constexpr int OFF_AL = PARTB;                 // valid when NPROD==2
    constexpr int OFF_B  = NPROD * PARTB;

    extern __shared__ char smem[];
    const uint32_t sbase = smem_u32(smem);
    const int tid  = threadIdx.x;
    const int lane = tid & 31;
    const int wid  = tid >> 5;
    const int wm   = wid & 3;
    const int wn   = wid >> 2;
    const int bm   = blockIdx.y * TM;
    const int bn   = blockIdx.x * TN;

    const int lrow  = lane & 15;
    const int lchun = lane >> 4;

    float acc[2][8][4];
#pragma unroll
    for (int i = 0; i < 2; i++)
#pragma unroll
        for (int j = 0; j < 8; j++)
#pragma unroll
            for (int q = 0; q < 4; q++) acc[i][j][q] = 0.f;

    const int S = K / TK;

    auto issue = [&](int s, int buf) {
        const uint32_t sb = sbase + buf * STAGE_SZ;
        const int k0 = s * TK;
#pragma unroll
        for (int i = 0; i < 2; i++) {
            int idx = tid + i * GT;
            int row = idx >> 2, seg = idx & 3;
            uint32_t sa = sb + row * ROWB + seg * 16;
            size_t go = (size_t)(bm + row) * K + k0 + seg * 8;
            cp16(sa, Ah + go);
            if (NPROD == 2) cp16(sa + OFF_AL, Al + go);
        }
#pragma unroll
        for (int i = 0; i < 2; i++) {
            int idx = tid + i * GT;
            int row = idx >> 2, seg = idx & 3;
            uint32_t sa = sb + OFF_B + row * ROWB + seg * 16;
            size_t go = (size_t)(bn + row) * K + k0 + seg * 8;
            cp16(sa, Bh + go);
        }
        cp_commit();
    };

    issue(0, 0);
    issue(1, 1);

    for (int s = 0; s < S; s++) {
        const int buf = s % STAGES;
        cp_wait<1>();
        __syncthreads();

        const uint32_t sb = sbase + buf * STAGE_SZ;
#pragma unroll
        for (int kk = 0; kk < 2; kk++) {
            const uint32_t koff = (uint32_t)((kk * 2 + lchun) * 16);
            uint32_t ah[2][4], al[2][4];
#pragma unroll
            for (int mt = 0; mt < 2; mt++) {
                uint32_t aa = sb + (uint32_t)((wm * 32 + mt * 16 + lrow) * ROWB) + koff;
                ldm_x4(ah[mt], aa);
                if (NPROD == 2) ldm_x4(al[mt], aa + OFF_AL);
            }
#pragma unroll
            for (int bg = 0; bg < 2; bg++) {
                uint32_t bh[2][4];
#pragma unroll
                for (int bt = 0; bt < 2; bt++) {
                    uint32_t ba = sb + OFF_B +
                        (uint32_t)((wn * 64 + (bg * 2 + bt) * 16 + lrow) * ROWB) + koff;
                    ldm_x4(bh[bt], ba);
                }
#pragma unroll
                for (int mt = 0; mt < 2; mt++)
#pragma unroll
                    for (int bt = 0; bt < 2; bt++)
#pragma unroll
                        for (int j = 0; j < 2; j++)
                            mma_f16(acc[mt][bg * 4 + bt * 2 + j], ah[mt], bh[bt][j], bh[bt][2 + j]);
                if (NPROD == 2) {
#pragma unroll
                    for (int mt = 0; mt < 2; mt++)
#pragma unroll
                        for (int bt = 0; bt < 2; bt++)
#pragma unroll
                            for (int j = 0; j < 2; j++)
                                mma_f16(acc[mt][bg * 4 + bt * 2 + j], al[mt], bh[bt][j], bh[bt][2 + j]);
                }
            }
        }
        if (s + 2 < S) issue(s + 2, (s + 2) % STAGES);
    }

    // epilogue
#pragma unroll
    for (int mt = 0; mt < 2; mt++)
#pragma unroll
        for (int nt = 0; nt < 8; nt++) {
            const int row0 = bm + wm * 32 + mt * 16 + (lane >> 2);
            const int col  = bn + wn * 64 + (nt >> 1) * 16 + (nt & 1) * 8 + (lane & 3) * 2;
#pragma unroll
            for (int h = 0; h < 2; h++) {
                const int r = row0 + h * 8;
                float2 v = make_float2(acc[mt][nt][2 * h + 0], acc[mt][nt][2 * h + 1]);
                if (EPI == EPI_KR) {
                    *reinterpret_cast<uint32_t*>(Oh + (size_t)r * N + col) = h2pack(v.x, v.y);
                }
                if (EPI == EPI_BIAS) {
                    float2 bb = *reinterpret_cast<const float2*>(bias + col);
                    v.x += bb.x; v.y += bb.y;
                    *reinterpret_cast<float2*>(C + (size_t)r * N + col) = v;
                }
                if (EPI == EPI_FF) {
                    if (col < NSplit) {
                        v.x = v.x > 0.f ? v.x * v.x : 0.f;
                        v.y = v.y > 0.f ? v.y * v.y : 0.f;
                        *reinterpret_cast<uint32_t*>(Oh + (size_t)r * NSplit + col) =
                            h2pack(v.x, v.y);
                    } else {
                        *reinterpret_cast<uint32_t*>(Or + (size_t)r * (N - NSplit) + col - NSplit) =
                            h2pack(v.x, v.y);
                    }
                }
                if (EPI == EPI_ADD) {
                    const size_t idx = (size_t)r * N + col;
                    float2 ci = *reinterpret_cast<const float2*>(Cin + idx);
                    v.x += ci.x; v.y += ci.y;
                    *reinterpret_cast<float2*>(C + idx) = v;
                }
                if (EPI == EPI_CMIX) {
                    const size_t idx = (size_t)r * N + col;
                    float2 ci = *reinterpret_cast<const float2*>(Cin + idx);
                    uint32_t rp = *reinterpret_cast<const uint32_t*>(Rg + idx);
                    float2 rr = __half22float2(*reinterpret_cast<const __half2*>(&rp));
                    v.x = ci.x + v.x * (1.f / (1.f + __expf(-rr.x)));
                    v.y = ci.y + v.y * (1.f / (1.f + __expf(-rr.y)));
                    *reinterpret_cast<float2*>(C + idx) = v;
                }
            }
        }
}

// ---------------------------------------------------------------------------
// LayerNorm over E=1024, warp-per-row: 256 threads = 8 warps = 8 rows/CTA.
// ---------------------------------------------------------------------------
__global__ __launch_bounds__(256)
void ln_kernel(const float* __restrict__ x, float* __restrict__ o,
               __half* __restrict__ oh,
               const float* __restrict__ g, const float* __restrict__ b)
{
    const int lane = threadIdx.x & 31;
    const int row  = blockIdx.x * 8 + (threadIdx.x >> 5);

    const float4* xr = reinterpret_cast<const float4*>(x + (size_t)row * E_DIM);
    float4 v[8];
    float s = 0.f, ss = 0.f;
#pragma unroll
    for (int i = 0; i < 8; i++) {
        v[i] = xr[lane + i * 32];
        s  += v[i].x + v[i].y + v[i].z + v[i].w;
        ss += v[i].x * v[i].x + v[i].y * v[i].y + v[i].z * v[i].z + v[i].w * v[i].w;
    }
#pragma unroll
    for (int off = 16; off > 0; off >>= 1) {
        s  += __shfl_xor_sync(0xffffffffu, s, off);
        ss += __shfl_xor_sync(0xffffffffu, ss, off);
    }
    const float mean = s * (1.f / E_DIM);
    const float inv  = rsqrtf(ss * (1.f / E_DIM) - mean * mean + 1e-5f);

#pragma unroll
    for (int i = 0; i < 8; i++) {
        const int c = lane + i * 32;
        float4 gg = reinterpret_cast<const float4*>(g)[c];
        float4 bb = reinterpret_cast<const float4*>(b)[c];
        float4 ov;
        ov.x = (v[i].x - mean) * inv * gg.x + bb.x;
        ov.y = (v[i].y - mean) * inv * gg.y + bb.y;
        ov.z = (v[i].z - mean) * inv * gg.z + bb.z;
        ov.w = (v[i].w - mean) * inv * gg.w + bb.w;
        if (o) reinterpret_cast<float4*>(o + (size_t)row * E_DIM)[c] = ov;
        if (oh) {
            uint2 hh;
            hh.x = h2pack(ov.x, ov.y);
            hh.y = h2pack(ov.z, ov.w);
            reinterpret_cast<uint2*>(oh + (size_t)row * E_DIM)[c] = hh;
        }
    }
}

// ---------------------------------------------------------------------------
// WKV recurrence, fused single kernel. Block = 1024 threads = 32 channels x
// 32 chunks of 32 steps; chunk states in smem; warp-uniform prefix; fp16 IO.
// kr layout: k at col e, v==r at col 1024+e, row stride 2048 (fp16).
// ---------------------------------------------------------------------------
__global__ __launch_bounds__(1024)
void wkv_fused(const __half* __restrict__ kr,
               const float* __restrict__ decay, const float* __restrict__ first,
               __half* __restrict__ yh)
{
    __shared__ float s_a[NCH2][32], s_b[NCH2][32], s_p[NCH2][32];
    const int ch = threadIdx.x & 31;
    const int c  = threadIdx.x >> 5;          // chunk, warp-uniform
    const int e  = blockIdx.x * 32 + ch;
    const int b  = blockIdx.y;
    const float w = -__expf(decay[e]);
    const float u = first[e];

    const size_t base  = ((size_t)b * T_LEN + (size_t)c * CLEN2) * 2048 + e;
    const size_t ybase = ((size_t)b * T_LEN + (size_t)c * CLEN2) * E_DIM + e;
    const __half* kp = kr + base;

    // pass 1: chunk-local scan from zero state
    float aa = 0.f, bb = 0.f, pp = -1e38f;
#pragma unroll 4
    for (int t = 0; t < CLEN2; t++) {
        float kt = __half2float(kp[(size_t)t * 2048]);
        float vt = __half2float(kp[(size_t)t * 2048 + 1024]);
        float ww = pp + w;
        float p  = fmaxf(ww, kt);
        float e1 = __expf(ww - p), e2 = __expf(kt - p);
        aa = e1 * aa + e2 * vt;
        bb = e1 * bb + e2;
        pp = p;
    }
    s_a[c][ch] = aa; s_b[c][ch] = bb; s_p[c][ch] = pp;
    __syncthreads();

    // prefix over previous chunks (<=31 iters, warp-uniform trip count)
    aa = 0.f; bb = 0.f; pp = -1e38f;
    for (int j = 0; j < c; j++) {
        float pd = pp + (float)CLEN2 * w;
        float a2 = s_a[j][ch], b2 = s_b[j][ch], p2 = s_p[j][ch];
        float p  = fmaxf(pd, p2);
        float e1 = __expf(pd - p), e2 = __expf(p2 - p);
        aa = e1 * aa + e2 * a2;
        bb = e1 * bb + e2 * b2;
        pp = p;
    }

    // replay emitting y = sigmoid(r) * wkv  (v == r)
    for (int t = 0; t < CLEN2; t++) {
        float kt = __half2float(kp[(size_t)t * 2048]);
        float vt = __half2float(kp[(size_t)t * 2048 + 1024]);
        float ww = u + kt;
        float p  = fmaxf(pp, ww);
        float e1 = __expf(pp - p), e2 = __expf(ww - p);
        float yt = (e1 * aa + e2 * vt) / (e1 * bb + e2);
        float ys = yt * (1.f / (1.f + __expf(-vt)));
        yh[ybase + (size_t)t * E_DIM] = __float2half_rn(ys);
        float ww2 = pp + w;
        float p2  = fmaxf(ww2, kt);
        e1 = __expf(ww2 - p2); e2 = __expf(kt - p2);
        aa = e1 * aa + e2 * vt;
        bb = e1 * bb + e2;
        pp = p2;
    }
}

// ---------------------------------------------------------------------------
// Host orchestration
// ---------------------------------------------------------------------------
static void set_smem_attrs() {
    cudaFuncSetAttribute(gemm_f16<EPI_BIAS, 2>, cudaFuncAttributeMaxDynamicSharedMemorySize, SMEM_NP2);
    cudaFuncSetAttribute(gemm_f16<EPI_KR,   1>, cudaFuncAttributeMaxDynamicSharedMemorySize, SMEM_NP1);
    cudaFuncSetAttribute(gemm_f16<EPI_FF,   1>, cudaFuncAttributeMaxDynamicSharedMemorySize, SMEM_NP1);
    cudaFuncSetAttribute(gemm_f16<EPI_ADD,  1>, cudaFuncAttributeMaxDynamicSharedMemorySize, SMEM_NP1);
    cudaFuncSetAttribute(gemm_f16<EPI_CMIX, 1>, cudaFuncAttributeMaxDynamicSharedMemorySize, SMEM_NP1);
}

extern "C" void kernel_launch(void* const* d_in, const int* in_sizes, int n_in,
                              void* d_out, int out_size)
{
    const float* inp    = (const float*)d_in[0];
    const float* W_in   = (const float*)d_in[1];
    const float* b_in   = (const float*)d_in[2];
    const float* ln0g   = (const float*)d_in[3];
    const float* ln0b   = (const float*)d_in[4];
    const float* l0ln1g = (const float*)d_in[5];
    const float* l0ln1b = (const float*)d_in[6];
    const float* l0ln2g = (const float*)d_in[7];
    const float* l0ln2b = (const float*)d_in[8];
    const float* l0cmk  = (const float*)d_in[9];
    const float* l0cmv  = (const float*)d_in[10];
    const float* l0cmr  = (const float*)d_in[11];
    const float* l0ffk  = (const float*)d_in[12];
    const float* l0ffv  = (const float*)d_in[13];
    const float* l0ffr  = (const float*)d_in[14];
    const float* tmk    = (const float*)d_in[15];
    const float* tmr    = (const float*)d_in[16];
    const float* tmo    = (const float*)d_in[17];
    const float* tmdec  = (const float*)d_in[18];
    const float* tmfst  = (const float*)d_in[19];
    const float* ln1g   = (const float*)d_in[20];
    const float* ln1b   = (const float*)d_in[21];
    const float* ln2g   = (const float*)d_in[22];
    const float* ln2b   = (const float*)d_in[23];
    const float* ffk    = (const float*)d_in[24];
    const float* ffv    = (const float*)d_in[25];
    const float* ffr    = (const float*)d_in[26];
    const float* outg   = (const float*)d_in[27];
    const float* outb   = (const float*)d_in[28];
    float* out = (float*)d_out;

    set_smem_attrs();

    __half *wf, *inh, *inl, *xnh, *hbh, *yh, *krh, *rh;
    float *res, *tmp;
    cudaGetSymbolAddress((void**)&wf,  g_wf);
    cudaGetSymbolAddress((void**)&inh, g_inh);
    cudaGetSymbolAddress((void**)&inl, g_inl);
    cudaGetSymbolAddress((void**)&xnh, g_xnh);
    cudaGetSymbolAddress((void**)&hbh, g_hbh);
    cudaGetSymbolAddress((void**)&yh,  g_yh);
    cudaGetSymbolAddress((void**)&krh, g_krh);
    cudaGetSymbolAddress((void**)&rh,  g_rh);
    cudaGetSymbolAddress((void**)&res, g_res);
    cudaGetSymbolAddress((void**)&tmp, g_tmp);

    // ---- weight conversion: one job-table launch ----
    ConvJobs jobs;
    size_t off = 0;
    int ji = 0;
    auto addjob = [&](const float* src, size_t n, size_t dofs) {
        jobs.src[ji] = src;
        jobs.n[ji]   = (unsigned long long)n;
        jobs.ofs[ji] = (unsigned long long)dofs;
        ji++;
    };
    auto alloc = [&](size_t n) -> size_t { size_t o = off; off += n; return o; };

    const size_t o_win = alloc((size_t)E_DIM * D_IN);
    addjob(W_in, (size_t)E_DIM * D_IN, o_win);
    const size_t o_cm = alloc(FFL_);                 // l0 cmk (4096) + cmr (1024)
    addjob(l0cmk, FE_, o_cm);
    addjob(l0cmr, EE_, o_cm + FE_);
    const size_t o_cmv = alloc(FE_);
    addjob(l0cmv, FE_, o_cmv);
    const size_t o_lff = alloc(FFL_);                // l0 ffk + ffr
    addjob(l0ffk, FE_, o_lff);
    addjob(l0ffr, EE_, o_lff + FE_);
    const size_t o_lffv = alloc(FE_);
    addjob(l0ffv, FE_, o_lffv);
    const size_t o_kr = alloc((size_t)NLAYER * KRL_);
    for (int l = 0; l < NLAYER; l++) {
        addjob(tmk + (size_t)l * EE_, EE_, o_kr + (size_t)l * KRL_);
        addjob(tmr + (size_t)l * EE_, EE_, o_kr + (size_t)l * KRL_ + EE_);
    }
    const size_t o_tmo = alloc((size_t)NLAYER * EE_);
    addjob(tmo, (size_t)NLAYER * EE_, o_tmo);
    const size_t o_ff = alloc((size_t)NLAYER * FFL_);
    for (int l = 0; l < NLAYER; l++) {
        addjob(ffk + (size_t)l * FE_, FE_, o_ff + (size_t)l * FFL_);
        addjob(ffr + (size_t)l * EE_, EE_, o_ff + (size_t)l * FFL_ + FE_);
    }
    const size_t o_ffv = alloc((size_t)NLAYER * FE_);
    addjob(ffv, (size_t)NLAYER * FE_, o_ffv);

    convert_w<<<dim3(640, NJOBS), 256>>>(jobs, wf);
    convert_pair<<<1024, 256>>>((const float4*)inp, (uint2*)inh, (uint2*)inl,
                                (int)((size_t)BTOK * D_IN / 4));

    const dim3 gE   (E_DIM / TN,  BTOK / TM);   // (8, 32)
    const dim3 gKR  (2048 / TN,   BTOK / TM);   // (16, 32)
    const dim3 gFF  (5120 / TN,   BTOK / TM);   // (40, 32)
    const dim3 gWKV (E_DIM / 32,  BATCH);       // (32, 4) x 1024 thr
    const int  gLN  = BTOK / 8;                 // 512 CTAs, warp-per-row

    // x = inputs @ W_in^T + b_in ; res = LN(x, ln0)
    gemm_f16<EPI_BIAS, 2><<<gE, GT, SMEM_NP2>>>(inh, inl, wf + o_win,
        tmp, BTOK, E_DIM, D_IN, b_in, nullptr, nullptr, nullptr, nullptr, 0);
    ln_kernel<<<gLN, 256>>>(tmp, res, nullptr, ln0g, ln0b);

    // channel mix (fused ffk+ffr GEMM 1-prod, ffv GEMM 1-prod, fp16 r gate)
    auto cmix = [&](const float* lg, const float* lb, size_t okr_, size_t ov_) {
        ln_kernel<<<gLN, 256>>>(res, nullptr, xnh, lg, lb);
        gemm_f16<EPI_FF, 1><<<gFF, GT, SMEM_NP1>>>(xnh, nullptr, wf + okr_,
            nullptr, BTOK, 5120, E_DIM, nullptr, nullptr, nullptr, hbh, rh, FOUR_E);
        gemm_f16<EPI_CMIX, 1><<<gE, GT, SMEM_NP1>>>(hbh, nullptr, wf + ov_,
            res, BTOK, E_DIM, FOUR_E, nullptr, res, rh, nullptr, nullptr, 0);
    };

    cmix(l0ln1g, l0ln1b, o_cm,  o_cmv);
    cmix(l0ln2g, l0ln2b, o_lff, o_lffv);

    for (int l = 0; l < NLAYER; l++) {
        const size_t oE = (size_t)l * E_DIM;

        ln_kernel<<<gLN, 256>>>(res, nullptr, xnh, ln1g + oE, ln1b + oE);
        gemm_f16<EPI_KR, 1><<<gKR, GT, SMEM_NP1>>>(xnh, nullptr, wf + o_kr + (size_t)l * KRL_,
            nullptr, BTOK, 2048, E_DIM, nullptr, nullptr, nullptr, krh, nullptr, 0);
        wkv_fused<<<gWKV, 1024>>>(krh, tmdec + oE, tmfst + oE, yh);
        gemm_f16<EPI_ADD, 1><<<gE, GT, SMEM_NP1>>>(yh, nullptr, wf + o_tmo + (size_t)l * EE_,
            res, BTOK, E_DIM, E_DIM, nullptr, res, nullptr, nullptr, nullptr, 0);

        ln_kernel<<<gLN, 256>>>(res, nullptr, xnh, ln2g + oE, ln2b + oE);
        gemm_f16<EPI_FF, 1><<<gFF, GT, SMEM_NP1>>>(xnh, nullptr, wf + o_ff + (size_t)l * FFL_,
            nullptr, BTOK, 5120, E_DIM, nullptr, nullptr, nullptr, hbh, rh, FOUR_E);
        gemm_f16<EPI_CMIX, 1><<<gE, GT, SMEM_NP1>>>(hbh, nullptr, wf + o_ffv + (size_t)l * FE_,
            res, BTOK, E_DIM, FOUR_E, nullptr, res, rh, nullptr, nullptr, 0);
    }

    ln_kernel<<<gLN, 256>>>(res, out, nullptr, outg, outb);
}